// round 1
// baseline (speedup 1.0000x reference)
#include <cuda_runtime.h>
#include <cuda_bf16.h>
#include <math.h>

// ---------------------------------------------------------------------------
// Problem constants
// ---------------------------------------------------------------------------
#define NL     12
#define DMODEL 768
#define NHEAD  12
#define DHEAD  64
#define FFDIM  3072
#define BATCH  2
#define QLEN   512
#define CLEN   2048
#define CHUNK  256
#define WINW   512   // j in [i, i+512]

// ---------------------------------------------------------------------------
// Scratch (device globals; allocation-free rule)
// ---------------------------------------------------------------------------
__device__ float g_hq [BATCH * QLEN * DMODEL];
__device__ float g_hc [BATCH * CLEN * DMODEL];
__device__ float g_q  [BATCH * CLEN * DMODEL];
__device__ float g_k  [BATCH * CLEN * DMODEL];
__device__ float g_v  [BATCH * CLEN * DMODEL];
__device__ float g_t  [BATCH * CLEN * DMODEL];
__device__ float g_t2 [BATCH * CLEN * DMODEL];
__device__ float g_ffn[BATCH * CLEN * FFDIM];
__device__ float g_sc [BATCH * CLEN * QLEN];
__device__ float g_re [BATCH * QLEN];

// ---------------------------------------------------------------------------
// Block reductions (256 threads)
// ---------------------------------------------------------------------------
__device__ __forceinline__ float block_reduce_sum(float v) {
    __shared__ float sh[33];
    int lane = threadIdx.x & 31, wid = threadIdx.x >> 5;
    #pragma unroll
    for (int o = 16; o; o >>= 1) v += __shfl_xor_sync(0xffffffffu, v, o);
    if (lane == 0) sh[wid] = v;
    __syncthreads();
    if (wid == 0) {
        float t = (lane < 8) ? sh[lane] : 0.f;
        #pragma unroll
        for (int o = 4; o; o >>= 1) t += __shfl_xor_sync(0xffffffffu, t, o);
        if (lane == 0) sh[32] = t;
    }
    __syncthreads();
    float r = sh[32];
    __syncthreads();
    return r;
}

__device__ __forceinline__ float block_reduce_max(float v) {
    __shared__ float sh[33];
    int lane = threadIdx.x & 31, wid = threadIdx.x >> 5;
    #pragma unroll
    for (int o = 16; o; o >>= 1) v = fmaxf(v, __shfl_xor_sync(0xffffffffu, v, o));
    if (lane == 0) sh[wid] = v;
    __syncthreads();
    if (wid == 0) {
        float t = (lane < 8) ? sh[lane] : -1e30f;
        #pragma unroll
        for (int o = 4; o; o >>= 1) t = fmaxf(t, __shfl_xor_sync(0xffffffffu, t, o));
        if (lane == 0) sh[32] = t;
    }
    __syncthreads();
    float r = sh[32];
    __syncthreads();
    return r;
}

// ---------------------------------------------------------------------------
// Embedding + LayerNorm (one block per token row, 256 threads, D=768)
// ---------------------------------------------------------------------------
__global__ void __launch_bounds__(256) embed_ln_kernel(
    const int* __restrict__ ids, const float* __restrict__ we,
    const float* __restrict__ pe, const float* __restrict__ te,
    const float* __restrict__ g, const float* __restrict__ b,
    float* __restrict__ h, int S)
{
    int row = blockIdx.x;
    int s = row % S;
    int tid = threadIdx.x;
    long long id = ids[row];
    const float* w = we + id * DMODEL;
    float x[3];
    #pragma unroll
    for (int l = 0; l < 3; l++) {
        int d = tid + l * 256;
        x[l] = w[d] + pe[(size_t)s * DMODEL + d] + te[d];
    }
    float mean = block_reduce_sum(x[0] + x[1] + x[2]) * (1.f / DMODEL);
    float vs = 0.f;
    #pragma unroll
    for (int l = 0; l < 3; l++) { float dd = x[l] - mean; vs += dd * dd; }
    float var = block_reduce_sum(vs) * (1.f / DMODEL);
    float rstd = rsqrtf(var + 1e-12f);
    size_t base = (size_t)row * DMODEL;
    #pragma unroll
    for (int l = 0; l < 3; l++) {
        int d = tid + l * 256;
        h[base + d] = (x[l] - mean) * rstd * g[d] + b[d];
    }
}

// h = LN(h + a) * g + b
__global__ void __launch_bounds__(256) add_ln_kernel(
    float* __restrict__ h, const float* __restrict__ a,
    const float* __restrict__ g, const float* __restrict__ b)
{
    int row = blockIdx.x;
    int tid = threadIdx.x;
    size_t base = (size_t)row * DMODEL;
    float x[3];
    #pragma unroll
    for (int l = 0; l < 3; l++) {
        int d = tid + l * 256;
        x[l] = h[base + d] + a[base + d];
    }
    float mean = block_reduce_sum(x[0] + x[1] + x[2]) * (1.f / DMODEL);
    float vs = 0.f;
    #pragma unroll
    for (int l = 0; l < 3; l++) { float dd = x[l] - mean; vs += dd * dd; }
    float var = block_reduce_sum(vs) * (1.f / DMODEL);
    float rstd = rsqrtf(var + 1e-12f);
    #pragma unroll
    for (int l = 0; l < 3; l++) {
        int d = tid + l * 256;
        h[base + d] = (x[l] - mean) * rstd * g[d] + b[d];
    }
}

// ---------------------------------------------------------------------------
// Tiled SGEMM: C[M,N] = epi(A[M,K] @ B[K,N] + bias)
// Requires M%64==0, N%64==0, K%16==0 (always true here).
// epi: 0 = none, 1 = *0.125 (q-scale), 2 = exact GELU
// ---------------------------------------------------------------------------
#define BM 64
#define BN 64
#define BK 16

__global__ void __launch_bounds__(256) gemm_nn(
    const float* __restrict__ A, const float* __restrict__ B,
    const float* __restrict__ bias, float* __restrict__ C,
    int M, int N, int K, int epi)
{
    __shared__ float As[BK][BM + 4];
    __shared__ float Bs[BK][BN + 4];
    int tid = threadIdx.x;
    int bm = blockIdx.y * BM;
    int bn = blockIdx.x * BN;
    int tx = tid & 15, ty = tid >> 4;

    int am = tid >> 2;            // 0..63
    int ak = (tid & 3) * 4;       // 0,4,8,12
    int br = tid >> 4;            // 0..15
    int bc = (tid & 15) * 4;      // 0..60

    const float* Aptr = A + (size_t)(bm + am) * K + ak;
    const float* Bptr = B + (size_t)br * N + bn + bc;

    float acc[4][4] = {};
    for (int k0 = 0; k0 < K; k0 += BK) {
        float4 a4 = *(const float4*)(Aptr + k0);
        float4 b4 = *(const float4*)(Bptr + (size_t)k0 * N);
        As[ak + 0][am] = a4.x; As[ak + 1][am] = a4.y;
        As[ak + 2][am] = a4.z; As[ak + 3][am] = a4.w;
        *(float4*)&Bs[br][bc] = b4;
        __syncthreads();
        #pragma unroll
        for (int kk = 0; kk < BK; kk++) {
            float a[4], b[4];
            #pragma unroll
            for (int i = 0; i < 4; i++) a[i] = As[kk][ty * 4 + i];
            #pragma unroll
            for (int j = 0; j < 4; j++) b[j] = Bs[kk][tx * 4 + j];
            #pragma unroll
            for (int i = 0; i < 4; i++)
                #pragma unroll
                for (int j = 0; j < 4; j++)
                    acc[i][j] += a[i] * b[j];
        }
        __syncthreads();
    }
    #pragma unroll
    for (int i = 0; i < 4; i++) {
        int r = bm + ty * 4 + i;
        #pragma unroll
        for (int j = 0; j < 4; j++) {
            int c = bn + tx * 4 + j;
            float v = acc[i][j];
            if (bias) v += bias[c];
            if (epi == 1) v *= 0.125f;
            else if (epi == 2) v = 0.5f * v * (1.f + erff(v * 0.7071067811865476f));
            C[(size_t)r * N + c] = v;
        }
    }
}

// C[M,N] = A[M,K] @ B[N,K]^T   (for interaction scores)
__global__ void __launch_bounds__(256) gemm_nt(
    const float* __restrict__ A, const float* __restrict__ B,
    float* __restrict__ C, int M, int N, int K)
{
    __shared__ float As[BK][BM + 4];
    __shared__ float Bs[BK][BN + 4];
    int tid = threadIdx.x;
    int bm = blockIdx.y * BM;
    int bn = blockIdx.x * BN;
    int tx = tid & 15, ty = tid >> 4;

    int am = tid >> 2;
    int ak = (tid & 3) * 4;
    int bnn = tid >> 2;           // 0..63  (column of C / row of B)
    int bk = (tid & 3) * 4;

    const float* Aptr = A + (size_t)(bm + am) * K + ak;
    const float* Bptr = B + (size_t)(bn + bnn) * K + bk;

    float acc[4][4] = {};
    for (int k0 = 0; k0 < K; k0 += BK) {
        float4 a4 = *(const float4*)(Aptr + k0);
        float4 b4 = *(const float4*)(Bptr + k0);
        As[ak + 0][am] = a4.x; As[ak + 1][am] = a4.y;
        As[ak + 2][am] = a4.z; As[ak + 3][am] = a4.w;
        Bs[bk + 0][bnn] = b4.x; Bs[bk + 1][bnn] = b4.y;
        Bs[bk + 2][bnn] = b4.z; Bs[bk + 3][bnn] = b4.w;
        __syncthreads();
        #pragma unroll
        for (int kk = 0; kk < BK; kk++) {
            float a[4], b[4];
            #pragma unroll
            for (int i = 0; i < 4; i++) a[i] = As[kk][ty * 4 + i];
            #pragma unroll
            for (int j = 0; j < 4; j++) b[j] = Bs[kk][tx * 4 + j];
            #pragma unroll
            for (int i = 0; i < 4; i++)
                #pragma unroll
                for (int j = 0; j < 4; j++)
                    acc[i][j] += a[i] * b[j];
        }
        __syncthreads();
    }
    #pragma unroll
    for (int i = 0; i < 4; i++)
        #pragma unroll
        for (int j = 0; j < 4; j++)
            C[(size_t)(bm + ty * 4 + i) * N + bn + tx * 4 + j] = acc[i][j];
}

// ---------------------------------------------------------------------------
// Sliding-window attention.
// Q/K/V: [B*S, 768] (head h at cols h*64..). One block per (chunk, head, b),
// one thread per query (256). Key window in 3-chunk coords: j in [i, i+512].
// Per-warp uniform key loop -> K/V loads are warp-broadcast.
// ---------------------------------------------------------------------------
__global__ void __launch_bounds__(256) local_attn_kernel(
    const float* __restrict__ Q, const float* __restrict__ K,
    const float* __restrict__ V, const int* __restrict__ mask,
    float* __restrict__ O, int nc, int S)
{
    int n = blockIdx.x, h = blockIdx.y, b = blockIdx.z;
    int i = threadIdx.x;
    int qrow = b * S + n * CHUNK + i;

    const float* qp = Q + (size_t)qrow * DMODEL + h * DHEAD;
    float q[DHEAD];
    #pragma unroll
    for (int d4 = 0; d4 < 16; d4++) {
        float4 t = *(const float4*)(qp + d4 * 4);
        q[d4*4+0] = t.x; q[d4*4+1] = t.y; q[d4*4+2] = t.z; q[d4*4+3] = t.w;
    }

    float m = -1e30f, l = 0.f;
    float acc[DHEAD];
    #pragma unroll
    for (int d = 0; d < DHEAD; d++) acc[d] = 0.f;

    int lane0 = i & ~31;
    int js = lane0;
    int je = min(lane0 + 31 + WINW, 3 * CHUNK - 1);

    for (int j = js; j <= je; j++) {
        int cn = n - 1 + (j >> 8);
        if (cn < 0 || cn >= nc) continue;                 // uniform
        int kpos = cn * CHUNK + (j & 255);
        if (mask[b * S + kpos] == 0) continue;            // uniform
        if (j < i || j > i + WINW) continue;              // band (per-lane)

        const float* kp = K + (size_t)(b * S + kpos) * DMODEL + h * DHEAD;
        float s = 0.f;
        #pragma unroll
        for (int d4 = 0; d4 < 16; d4++) {
            float4 kv = *(const float4*)(kp + d4 * 4);
            s += q[d4*4+0]*kv.x + q[d4*4+1]*kv.y + q[d4*4+2]*kv.z + q[d4*4+3]*kv.w;
        }
        float nm = fmaxf(m, s);
        float corr = __expf(m - nm);
        float p = __expf(s - nm);
        l = l * corr + p;
        m = nm;
        const float* vp = V + (size_t)(b * S + kpos) * DMODEL + h * DHEAD;
        #pragma unroll
        for (int d4 = 0; d4 < 16; d4++) {
            float4 vv = *(const float4*)(vp + d4 * 4);
            acc[d4*4+0] = acc[d4*4+0]*corr + p*vv.x;
            acc[d4*4+1] = acc[d4*4+1]*corr + p*vv.y;
            acc[d4*4+2] = acc[d4*4+2]*corr + p*vv.z;
            acc[d4*4+3] = acc[d4*4+3]*corr + p*vv.w;
        }
    }
    float inv = 1.f / l;
    float* op = O + (size_t)qrow * DMODEL + h * DHEAD;
    #pragma unroll
    for (int d4 = 0; d4 < 16; d4++) {
        float4 o4;
        o4.x = acc[d4*4+0]*inv; o4.y = acc[d4*4+1]*inv;
        o4.z = acc[d4*4+2]*inv; o4.w = acc[d4*4+3]*inv;
        *(float4*)(op + d4 * 4) = o4;
    }
}

// ---------------------------------------------------------------------------
// Interaction head kernels
// ---------------------------------------------------------------------------
// softmax over last dim (QLEN=512) in place; one block per row of P
__global__ void __launch_bounds__(256) softmax_row_kernel(float* __restrict__ P)
{
    int row = blockIdx.x, tid = threadIdx.x;
    float* p = P + (size_t)row * QLEN;
    float x0 = p[tid], x1 = p[tid + 256];
    float m = block_reduce_max(fmaxf(x0, x1));
    float e0 = __expf(x0 - m), e1 = __expf(x1 - m);
    float s = block_reduce_sum(e0 + e1);
    float inv = 1.f / s;
    p[tid] = e0 * inv;
    p[tid + 256] = e1 * inv;
}

// re[b][q] = max over c of P[b][c][q]
__global__ void __launch_bounds__(256) colmax_kernel(
    const float* __restrict__ P, float* __restrict__ re)
{
    int b = blockIdx.x;
    int q = blockIdx.y * 256 + threadIdx.x;
    const float* p = P + (size_t)b * CLEN * QLEN + q;
    float m = -1e30f;
    for (int r = 0; r < CLEN; r++) m = fmaxf(m, p[(size_t)r * QLEN]);
    re[b * QLEN + q] = m;
}

// out[b][o] = re[b] . fc_w[:,o] + fc_b[o]
__global__ void fc_kernel(const float* __restrict__ re, const float* __restrict__ w,
                          const float* __restrict__ bfc, float* __restrict__ out)
{
    int t = threadIdx.x;
    if (t >= 8) return;
    int b = t >> 2, o = t & 3;
    float s = bfc[o];
    for (int q = 0; q < QLEN; q++) s += re[b * QLEN + q] * w[q * 4 + o];
    out[b * 4 + o] = s;
}

// ---------------------------------------------------------------------------
// Host orchestration
// ---------------------------------------------------------------------------
extern "C" void kernel_launch(void* const* d_in, const int* in_sizes, int n_in,
                              void* d_out, int out_size)
{
    const int*   q_ids    = (const int*)  d_in[0];
    const int*   c_ids    = (const int*)  d_in[1];
    const int*   q_mask   = (const int*)  d_in[2];
    const int*   c_mask   = (const int*)  d_in[3];
    const float* word_emb = (const float*)d_in[4];
    const float* pos_emb  = (const float*)d_in[5];
    const float* type_emb = (const float*)d_in[6];
    const float* eg       = (const float*)d_in[7];
    const float* eb       = (const float*)d_in[8];
    const float* Wq  = (const float*)d_in[9];
    const float* bq  = (const float*)d_in[10];
    const float* Wk  = (const float*)d_in[11];
    const float* bk  = (const float*)d_in[12];
    const float* Wv  = (const float*)d_in[13];
    const float* bv  = (const float*)d_in[14];
    const float* Wo  = (const float*)d_in[15];
    const float* bo  = (const float*)d_in[16];
    const float* l1g = (const float*)d_in[17];
    const float* l1b = (const float*)d_in[18];
    const float* W1  = (const float*)d_in[19];
    const float* b1  = (const float*)d_in[20];
    const float* W2  = (const float*)d_in[21];
    const float* b2  = (const float*)d_in[22];
    const float* l2g = (const float*)d_in[23];
    const float* l2b = (const float*)d_in[24];
    const float* fcw = (const float*)d_in[25];
    const float* fcb = (const float*)d_in[26];

    float *hq, *hc, *sq, *sk, *sv, *st, *st2, *sffn, *ssc, *sre;
    cudaGetSymbolAddress((void**)&hq,  g_hq);
    cudaGetSymbolAddress((void**)&hc,  g_hc);
    cudaGetSymbolAddress((void**)&sq,  g_q);
    cudaGetSymbolAddress((void**)&sk,  g_k);
    cudaGetSymbolAddress((void**)&sv,  g_v);
    cudaGetSymbolAddress((void**)&st,  g_t);
    cudaGetSymbolAddress((void**)&st2, g_t2);
    cudaGetSymbolAddress((void**)&sffn,g_ffn);
    cudaGetSymbolAddress((void**)&ssc, g_sc);
    cudaGetSymbolAddress((void**)&sre, g_re);

    const size_t D2 = (size_t)DMODEL * DMODEL;
    const size_t DF = (size_t)DMODEL * FFDIM;

    auto encode = [&](const int* ids, const int* mask, int S, float* h) {
        int rows = BATCH * S;
        int nc = S / CHUNK;
        embed_ln_kernel<<<rows, 256>>>(ids, word_emb, pos_emb, type_emb, eg, eb, h, S);
        for (int l = 0; l < NL; l++) {
            dim3 gD(DMODEL / BN, rows / BM);
            dim3 gF(FFDIM  / BN, rows / BM);
            gemm_nn<<<gD, 256>>>(h, Wq + l * D2, bq + l * DMODEL, sq, rows, DMODEL, DMODEL, 1);
            gemm_nn<<<gD, 256>>>(h, Wk + l * D2, bk + l * DMODEL, sk, rows, DMODEL, DMODEL, 0);
            gemm_nn<<<gD, 256>>>(h, Wv + l * D2, bv + l * DMODEL, sv, rows, DMODEL, DMODEL, 0);
            local_attn_kernel<<<dim3(nc, NHEAD, BATCH), 256>>>(sq, sk, sv, mask, st, nc, S);
            gemm_nn<<<gD, 256>>>(st, Wo + l * D2, bo + l * DMODEL, st2, rows, DMODEL, DMODEL, 0);
            add_ln_kernel<<<rows, 256>>>(h, st2, l1g + l * DMODEL, l1b + l * DMODEL);
            gemm_nn<<<gF, 256>>>(h, W1 + l * DF, b1 + l * FFDIM, sffn, rows, FFDIM, DMODEL, 2);
            gemm_nn<<<gD, 256>>>(sffn, W2 + l * DF, b2 + l * DMODEL, st2, rows, DMODEL, FFDIM, 0);
            add_ln_kernel<<<rows, 256>>>(h, st2, l2g + l * DMODEL, l2b + l * DMODEL);
        }
    };

    encode(q_ids, q_mask, QLEN, hq);
    encode(c_ids, c_mask, CLEN, hc);

    // scores[b] = c_h[b] @ q_h[b]^T   -> [CLEN, QLEN]
    for (int b = 0; b < BATCH; b++) {
        gemm_nt<<<dim3(QLEN / BN, CLEN / BM), 256>>>(
            hc + (size_t)b * CLEN * DMODEL,
            hq + (size_t)b * QLEN * DMODEL,
            ssc + (size_t)b * CLEN * QLEN,
            CLEN, QLEN, DMODEL);
    }
    softmax_row_kernel<<<BATCH * CLEN, 256>>>(ssc);
    colmax_kernel<<<dim3(BATCH, QLEN / 256), 256>>>(ssc, sre);
    fc_kernel<<<1, 32>>>(sre, fcw, fcb, (float*)d_out);
}

// round 3
// speedup vs baseline: 1.3200x; 1.3200x over previous
#include <cuda_runtime.h>
#include <cuda_bf16.h>
#include <math.h>
#include <stdint.h>

// ---------------------------------------------------------------------------
// Problem constants
// ---------------------------------------------------------------------------
#define NL     12
#define DMODEL 768
#define NHEAD  12
#define DHEAD  64
#define FFDIM  3072
#define BATCH  2
#define QLEN   512
#define CLEN   2048
#define CHUNK  256
#define WINW   512

// ---------------------------------------------------------------------------
// PTX helpers (baseline sm_80+ features only — no tcgen05 on plain sm_103 target)
// ---------------------------------------------------------------------------
__device__ __forceinline__ uint32_t smem_u32(const void* p) {
    uint32_t a;
    asm("{ .reg .u64 t; cvta.to.shared.u64 t, %1; cvt.u32.u64 %0, t; }" : "=r"(a) : "l"(p));
    return a;
}

__device__ __forceinline__ void ldsm_x4(uint32_t* r, uint32_t addr) {
    asm volatile("ldmatrix.sync.aligned.m8n8.x4.shared.b16 {%0,%1,%2,%3}, [%4];"
                 : "=r"(r[0]), "=r"(r[1]), "=r"(r[2]), "=r"(r[3]) : "r"(addr));
}

__device__ __forceinline__ void mma_bf16(float* c, const uint32_t* a, uint32_t b0, uint32_t b1) {
    asm volatile(
        "mma.sync.aligned.m16n8k16.row.col.f32.bf16.bf16.f32 "
        "{%0,%1,%2,%3}, {%4,%5,%6,%7}, {%8,%9}, {%0,%1,%2,%3};"
        : "+f"(c[0]), "+f"(c[1]), "+f"(c[2]), "+f"(c[3])
        : "r"(a[0]), "r"(a[1]), "r"(a[2]), "r"(a[3]), "r"(b0), "r"(b1));
}

#define CP_ASYNC16(dst, src) \
    asm volatile("cp.async.cg.shared.global [%0], [%1], 16;" :: "r"(dst), "l"(src))
#define CP_COMMIT() asm volatile("cp.async.commit_group;")
#define CP_WAIT(n)  asm volatile("cp.async.wait_group %0;" :: "n"(n))

// ---------------------------------------------------------------------------
// Scratch (device globals)
// ---------------------------------------------------------------------------
#define LW   7077888ull
#define WTOT (12ull * LW)
#define OFF_Q  0ull
#define OFF_K  589824ull
#define OFF_V  1179648ull
#define OFF_O  1769472ull
#define OFF_W1 2359296ull
#define OFF_W2 4718592ull

__device__ __nv_bfloat16 g_w_hi[WTOT];
__device__ __nv_bfloat16 g_w_lo[WTOT];

__device__ float g_hq [BATCH * QLEN * DMODEL];
__device__ float g_hc [BATCH * CLEN * DMODEL];
__device__ __nv_bfloat16 g_hq_hi[BATCH * QLEN * DMODEL];
__device__ __nv_bfloat16 g_hq_lo[BATCH * QLEN * DMODEL];
__device__ __nv_bfloat16 g_hc_hi[BATCH * CLEN * DMODEL];
__device__ __nv_bfloat16 g_hc_lo[BATCH * CLEN * DMODEL];

__device__ float g_q  [BATCH * CLEN * DMODEL];
__device__ float g_k  [BATCH * CLEN * DMODEL];
__device__ float g_v  [BATCH * CLEN * DMODEL];
__device__ float g_t2 [BATCH * CLEN * DMODEL];
__device__ __nv_bfloat16 g_st_hi[BATCH * CLEN * DMODEL];
__device__ __nv_bfloat16 g_st_lo[BATCH * CLEN * DMODEL];
__device__ __nv_bfloat16 g_ffn_hi[BATCH * CLEN * FFDIM];
__device__ __nv_bfloat16 g_ffn_lo[BATCH * CLEN * FFDIM];

__device__ float g_sc [BATCH * CLEN * QLEN];
__device__ float g_re [BATCH * QLEN];

// ---------------------------------------------------------------------------
// Reductions
// ---------------------------------------------------------------------------
__device__ __forceinline__ float block_reduce_sum(float v) {
    __shared__ float sh[33];
    int lane = threadIdx.x & 31, wid = threadIdx.x >> 5;
    #pragma unroll
    for (int o = 16; o; o >>= 1) v += __shfl_xor_sync(0xffffffffu, v, o);
    if (lane == 0) sh[wid] = v;
    __syncthreads();
    if (wid == 0) {
        float t = (lane < 8) ? sh[lane] : 0.f;
        #pragma unroll
        for (int o = 4; o; o >>= 1) t += __shfl_xor_sync(0xffffffffu, t, o);
        if (lane == 0) sh[32] = t;
    }
    __syncthreads();
    float r = sh[32];
    __syncthreads();
    return r;
}
__device__ __forceinline__ float block_reduce_max(float v) {
    __shared__ float sh[33];
    int lane = threadIdx.x & 31, wid = threadIdx.x >> 5;
    #pragma unroll
    for (int o = 16; o; o >>= 1) v = fmaxf(v, __shfl_xor_sync(0xffffffffu, v, o));
    if (lane == 0) sh[wid] = v;
    __syncthreads();
    if (wid == 0) {
        float t = (lane < 8) ? sh[lane] : -1e30f;
        #pragma unroll
        for (int o = 4; o; o >>= 1) t = fmaxf(t, __shfl_xor_sync(0xffffffffu, t, o));
        if (lane == 0) sh[32] = t;
    }
    __syncthreads();
    float r = sh[32];
    __syncthreads();
    return r;
}

__device__ __forceinline__ void split_bf16(float x, __nv_bfloat16& hi, __nv_bfloat16& lo) {
    hi = __float2bfloat16(x);
    lo = __float2bfloat16(x - __bfloat162float(hi));
}

// ---------------------------------------------------------------------------
// Weight transpose + split: W[K,N] -> Thi/Tlo[N,K]
// ---------------------------------------------------------------------------
__global__ void __launch_bounds__(256) wprep_kernel(
    const float* __restrict__ W, __nv_bfloat16* __restrict__ Thi,
    __nv_bfloat16* __restrict__ Tlo, int K, int N)
{
    __shared__ float t[32][33];
    int tx = threadIdx.x & 31, ty = threadIdx.x >> 5;
    int n0 = blockIdx.x * 32, k0 = blockIdx.y * 32;
    #pragma unroll
    for (int j = 0; j < 4; j++)
        t[ty + 8 * j][tx] = W[(size_t)(k0 + ty + 8 * j) * N + n0 + tx];
    __syncthreads();
    #pragma unroll
    for (int j = 0; j < 4; j++) {
        int n = n0 + ty + 8 * j, k = k0 + tx;
        float v = t[tx][ty + 8 * j];
        __nv_bfloat16 hi, lo;
        split_bf16(v, hi, lo);
        Thi[(size_t)n * K + k] = hi;
        Tlo[(size_t)n * K + k] = lo;
    }
}

// ---------------------------------------------------------------------------
// Embedding + LN (writes fp32 + hi/lo)
// ---------------------------------------------------------------------------
__global__ void __launch_bounds__(256) embed_ln_kernel(
    const int* __restrict__ ids, const float* __restrict__ we,
    const float* __restrict__ pe, const float* __restrict__ te,
    const float* __restrict__ g, const float* __restrict__ b,
    float* __restrict__ h, __nv_bfloat16* __restrict__ hhi,
    __nv_bfloat16* __restrict__ hlo, int S)
{
    int row = blockIdx.x;
    int s = row % S;
    int tid = threadIdx.x;
    long long id = ids[row];
    const float* w = we + id * DMODEL;
    float x[3];
    #pragma unroll
    for (int l = 0; l < 3; l++) {
        int d = tid + l * 256;
        x[l] = w[d] + pe[(size_t)s * DMODEL + d] + te[d];
    }
    float mean = block_reduce_sum(x[0] + x[1] + x[2]) * (1.f / DMODEL);
    float vs = 0.f;
    #pragma unroll
    for (int l = 0; l < 3; l++) { float dd = x[l] - mean; vs += dd * dd; }
    float rstd = rsqrtf(block_reduce_sum(vs) * (1.f / DMODEL) + 1e-12f);
    size_t base = (size_t)row * DMODEL;
    #pragma unroll
    for (int l = 0; l < 3; l++) {
        int d = tid + l * 256;
        float y = (x[l] - mean) * rstd * g[d] + b[d];
        h[base + d] = y;
        __nv_bfloat16 hi, lo; split_bf16(y, hi, lo);
        hhi[base + d] = hi; hlo[base + d] = lo;
    }
}

__global__ void __launch_bounds__(256) add_ln_kernel(
    float* __restrict__ h, const float* __restrict__ a,
    const float* __restrict__ g, const float* __restrict__ b,
    __nv_bfloat16* __restrict__ hhi, __nv_bfloat16* __restrict__ hlo)
{
    int row = blockIdx.x;
    int tid = threadIdx.x;
    size_t base = (size_t)row * DMODEL;
    float x[3];
    #pragma unroll
    for (int l = 0; l < 3; l++) {
        int d = tid + l * 256;
        x[l] = h[base + d] + a[base + d];
    }
    float mean = block_reduce_sum(x[0] + x[1] + x[2]) * (1.f / DMODEL);
    float vs = 0.f;
    #pragma unroll
    for (int l = 0; l < 3; l++) { float dd = x[l] - mean; vs += dd * dd; }
    float rstd = rsqrtf(block_reduce_sum(vs) * (1.f / DMODEL) + 1e-12f);
    #pragma unroll
    for (int l = 0; l < 3; l++) {
        int d = tid + l * 256;
        float y = (x[l] - mean) * rstd * g[d] + b[d];
        h[base + d] = y;
        __nv_bfloat16 hi, lo; split_bf16(y, hi, lo);
        hhi[base + d] = hi; hlo[base + d] = lo;
    }
}

// ---------------------------------------------------------------------------
// Split-bf16 HMMA GEMM: C[M,N] = A[M,K] @ B[N,K]^T  (3-product Markidis)
// CTA tile 128x128, BK=32, cp.async double buffer, 8 warps of 32x64.
// epi: 0 = bias + fp32, 1 = bias + *0.125 + fp32, 2 = bias + GELU + bf16 hi/lo
// ---------------------------------------------------------------------------
#define ROWB   40                      // bf16 per padded smem row (80 bytes)
#define TILE_B (128 * ROWB * 2)        // 10240 bytes per tile
#define SMEMSZ (8 * TILE_B)            // 2 buffers x 4 tiles = 81920

__global__ void __launch_bounds__(256) mma_gemm(
    const __nv_bfloat16* __restrict__ Ahi, const __nv_bfloat16* __restrict__ Alo,
    const __nv_bfloat16* __restrict__ Bhi, const __nv_bfloat16* __restrict__ Blo,
    const float* __restrict__ bias,
    float* __restrict__ Cf, __nv_bfloat16* __restrict__ Chi, __nv_bfloat16* __restrict__ Clo,
    int M, int N, int K, int epi)
{
    extern __shared__ char smem[];
    uint32_t sbase = smem_u32(smem);
    int tid = threadIdx.x, lane = tid & 31, wid = tid >> 5;
    int wm = wid & 3, wn = wid >> 2;             // 4 x 2 warp grid
    int bm = blockIdx.y * 128, bn = blockIdx.x * 128;
    int nkt = K >> 5;

    float acc[2][8][4] = {};                      // [mt][nt*2+n8][4]

    int lrow = tid >> 2;                          // 0..63
    int lc16 = tid & 3;

    auto load_stage = [&](int buf, int kt) {
        int kb = kt * 32 + lc16 * 8;
        uint32_t dbase = sbase + buf * (4 * TILE_B);
        #pragma unroll
        for (int c = 0; c < 2; c++) {
            int row = lrow + c * 64;
            uint32_t so = (uint32_t)(row * 80 + lc16 * 16);
            const __nv_bfloat16* pa = Ahi + (size_t)(bm + row) * K + kb;
            const __nv_bfloat16* pb = Alo + (size_t)(bm + row) * K + kb;
            const __nv_bfloat16* pc = Bhi + (size_t)(bn + row) * K + kb;
            const __nv_bfloat16* pd = Blo + (size_t)(bn + row) * K + kb;
            CP_ASYNC16(dbase + 0 * TILE_B + so, pa);
            CP_ASYNC16(dbase + 1 * TILE_B + so, pb);
            CP_ASYNC16(dbase + 2 * TILE_B + so, pc);
            CP_ASYNC16(dbase + 3 * TILE_B + so, pd);
        }
        CP_COMMIT();
    };

    load_stage(0, 0);

    for (int kt = 0; kt < nkt; kt++) {
        int cur = kt & 1;
        if (kt + 1 < nkt) { load_stage(cur ^ 1, kt + 1); CP_WAIT(1); }
        else              { CP_WAIT(0); }
        __syncthreads();

        uint32_t abase = sbase + cur * (4 * TILE_B);
        #pragma unroll
        for (int ks = 0; ks < 2; ks++) {
            uint32_t koff = (uint32_t)((ks * 16 + (lane >> 4) * 8) * 2);
            uint32_t ah[2][4], al[2][4];
            #pragma unroll
            for (int mt = 0; mt < 2; mt++) {
                uint32_t r = abase + (uint32_t)((wm * 32 + mt * 16 + (lane & 15)) * 80) + koff;
                ldsm_x4(ah[mt], r);
                ldsm_x4(al[mt], r + TILE_B);
            }
            #pragma unroll
            for (int nt = 0; nt < 4; nt++) {
                uint32_t bh[4], bl[4];
                uint32_t r = abase + 2 * TILE_B
                           + (uint32_t)((wn * 64 + nt * 16 + (lane & 15)) * 80) + koff;
                ldsm_x4(bh, r);
                ldsm_x4(bl, r + TILE_B);
                #pragma unroll
                for (int mt = 0; mt < 2; mt++) {
                    mma_bf16(acc[mt][nt * 2 + 0], ah[mt], bh[0], bh[2]);
                    mma_bf16(acc[mt][nt * 2 + 0], ah[mt], bl[0], bl[2]);
                    mma_bf16(acc[mt][nt * 2 + 0], al[mt], bh[0], bh[2]);
                    mma_bf16(acc[mt][nt * 2 + 1], ah[mt], bh[1], bh[3]);
                    mma_bf16(acc[mt][nt * 2 + 1], ah[mt], bl[1], bl[3]);
                    mma_bf16(acc[mt][nt * 2 + 1], al[mt], bh[1], bh[3]);
                }
            }
        }
        __syncthreads();
    }

    // epilogue
    int g = lane >> 2, t4 = lane & 3;
    #pragma unroll
    for (int mt = 0; mt < 2; mt++) {
        #pragma unroll
        for (int nt = 0; nt < 4; nt++) {
            #pragma unroll
            for (int h8 = 0; h8 < 2; h8++) {
                float* d = acc[mt][nt * 2 + h8];
                int c0 = bn + wn * 64 + nt * 16 + h8 * 8 + t4 * 2;
                #pragma unroll
                for (int rr = 0; rr < 2; rr++) {
                    int r = bm + wm * 32 + mt * 16 + g + rr * 8;
                    float v0 = d[rr * 2 + 0], v1 = d[rr * 2 + 1];
                    if (bias) { v0 += __ldg(bias + c0); v1 += __ldg(bias + c0 + 1); }
                    if (epi == 1) { v0 *= 0.125f; v1 *= 0.125f; }
                    else if (epi == 2) {
                        v0 = 0.5f * v0 * (1.f + erff(v0 * 0.7071067811865476f));
                        v1 = 0.5f * v1 * (1.f + erff(v1 * 0.7071067811865476f));
                        __nv_bfloat16 h0, l0, h1, l1;
                        split_bf16(v0, h0, l0); split_bf16(v1, h1, l1);
                        size_t idx = (size_t)r * N + c0;
                        *(__nv_bfloat162*)&Chi[idx] = __nv_bfloat162(h0, h1);
                        *(__nv_bfloat162*)&Clo[idx] = __nv_bfloat162(l0, l1);
                        continue;
                    }
                    float2 o; o.x = v0; o.y = v1;
                    *(float2*)&Cf[(size_t)r * N + c0] = o;
                }
            }
        }
    }
}

// ---------------------------------------------------------------------------
// Sliding-window attention (fp32 in, bf16 hi/lo out)
// ---------------------------------------------------------------------------
__global__ void __launch_bounds__(256) local_attn_kernel(
    const float* __restrict__ Q, const float* __restrict__ K,
    const float* __restrict__ V, const int* __restrict__ mask,
    __nv_bfloat16* __restrict__ Ohi, __nv_bfloat16* __restrict__ Olo,
    int nc, int S)
{
    int n = blockIdx.x, h = blockIdx.y, b = blockIdx.z;
    int i = threadIdx.x;
    int qrow = b * S + n * CHUNK + i;

    const float* qp = Q + (size_t)qrow * DMODEL + h * DHEAD;
    float q[DHEAD];
    #pragma unroll
    for (int d4 = 0; d4 < 16; d4++) {
        float4 t = *(const float4*)(qp + d4 * 4);
        q[d4*4+0] = t.x; q[d4*4+1] = t.y; q[d4*4+2] = t.z; q[d4*4+3] = t.w;
    }

    float m = -1e30f, l = 0.f;
    float acc[DHEAD];
    #pragma unroll
    for (int d = 0; d < DHEAD; d++) acc[d] = 0.f;

    int lane0 = i & ~31;
    int js = lane0;
    int je = min(lane0 + 31 + WINW, 3 * CHUNK - 1);

    for (int j = js; j <= je; j++) {
        int cn = n - 1 + (j >> 8);
        if (cn < 0 || cn >= nc) continue;
        int kpos = cn * CHUNK + (j & 255);
        if (mask[b * S + kpos] == 0) continue;
        if (j < i || j > i + WINW) continue;

        const float* kp = K + (size_t)(b * S + kpos) * DMODEL + h * DHEAD;
        float s = 0.f;
        #pragma unroll
        for (int d4 = 0; d4 < 16; d4++) {
            float4 kv = *(const float4*)(kp + d4 * 4);
            s += q[d4*4+0]*kv.x + q[d4*4+1]*kv.y + q[d4*4+2]*kv.z + q[d4*4+3]*kv.w;
        }
        float nm = fmaxf(m, s);
        float corr = __expf(m - nm);
        float p = __expf(s - nm);
        l = l * corr + p;
        m = nm;
        const float* vp = V + (size_t)(b * S + kpos) * DMODEL + h * DHEAD;
        #pragma unroll
        for (int d4 = 0; d4 < 16; d4++) {
            float4 vv = *(const float4*)(vp + d4 * 4);
            acc[d4*4+0] = acc[d4*4+0]*corr + p*vv.x;
            acc[d4*4+1] = acc[d4*4+1]*corr + p*vv.y;
            acc[d4*4+2] = acc[d4*4+2]*corr + p*vv.z;
            acc[d4*4+3] = acc[d4*4+3]*corr + p*vv.w;
        }
    }
    float inv = 1.f / l;
    size_t ob = (size_t)qrow * DMODEL + h * DHEAD;
    #pragma unroll
    for (int d = 0; d < DHEAD; d++) {
        float val = acc[d] * inv;
        __nv_bfloat16 hi, lo; split_bf16(val, hi, lo);
        Ohi[ob + d] = hi; Olo[ob + d] = lo;
    }
}

// ---------------------------------------------------------------------------
// Interaction head
// ---------------------------------------------------------------------------
__global__ void __launch_bounds__(256) softmax_row_kernel(float* __restrict__ P)
{
    int row = blockIdx.x, tid = threadIdx.x;
    float* p = P + (size_t)row * QLEN;
    float x0 = p[tid], x1 = p[tid + 256];
    float m = block_reduce_max(fmaxf(x0, x1));
    float e0 = __expf(x0 - m), e1 = __expf(x1 - m);
    float s = block_reduce_sum(e0 + e1);
    float inv = 1.f / s;
    p[tid] = e0 * inv;
    p[tid + 256] = e1 * inv;
}

__global__ void __launch_bounds__(256) colmax_kernel(
    const float* __restrict__ P, float* __restrict__ re)
{
    int b = blockIdx.x;
    int q = blockIdx.y * 256 + threadIdx.x;
    const float* p = P + (size_t)b * CLEN * QLEN + q;
    float m = -1e30f;
    for (int r = 0; r < CLEN; r++) m = fmaxf(m, p[(size_t)r * QLEN]);
    re[b * QLEN + q] = m;
}

__global__ void fc_kernel(const float* __restrict__ re, const float* __restrict__ w,
                          const float* __restrict__ bfc, float* __restrict__ out)
{
    int t = threadIdx.x;
    if (t >= 8) return;
    int b = t >> 2, o = t & 3;
    float s = bfc[o];
    for (int q = 0; q < QLEN; q++) s += re[b * QLEN + q] * w[q * 4 + o];
    out[b * 4 + o] = s;
}

// ---------------------------------------------------------------------------
// Host orchestration
// ---------------------------------------------------------------------------
extern "C" void kernel_launch(void* const* d_in, const int* in_sizes, int n_in,
                              void* d_out, int out_size)
{
    const int*   q_ids    = (const int*)  d_in[0];
    const int*   c_ids    = (const int*)  d_in[1];
    const int*   q_mask   = (const int*)  d_in[2];
    const int*   c_mask   = (const int*)  d_in[3];
    const float* word_emb = (const float*)d_in[4];
    const float* pos_emb  = (const float*)d_in[5];
    const float* type_emb = (const float*)d_in[6];
    const float* eg       = (const float*)d_in[7];
    const float* eb       = (const float*)d_in[8];
    const float* Wq  = (const float*)d_in[9];
    const float* bq  = (const float*)d_in[10];
    const float* Wk  = (const float*)d_in[11];
    const float* bk  = (const float*)d_in[12];
    const float* Wv  = (const float*)d_in[13];
    const float* bv  = (const float*)d_in[14];
    const float* Wo  = (const float*)d_in[15];
    const float* bo  = (const float*)d_in[16];
    const float* l1g = (const float*)d_in[17];
    const float* l1b = (const float*)d_in[18];
    const float* W1  = (const float*)d_in[19];
    const float* b1  = (const float*)d_in[20];
    const float* W2  = (const float*)d_in[21];
    const float* b2  = (const float*)d_in[22];
    const float* l2g = (const float*)d_in[23];
    const float* l2b = (const float*)d_in[24];
    const float* fcw = (const float*)d_in[25];
    const float* fcb = (const float*)d_in[26];

    cudaFuncSetAttribute(mma_gemm, cudaFuncAttributeMaxDynamicSharedMemorySize, SMEMSZ);

    __nv_bfloat16 *whi, *wlo, *hqhi, *hqlo, *hchi, *hclo, *sthi, *stlo, *ffnhi, *ffnlo;
    float *hq, *hc, *sq, *sk, *sv, *st2, *ssc, *sre;
    cudaGetSymbolAddress((void**)&whi,  g_w_hi);
    cudaGetSymbolAddress((void**)&wlo,  g_w_lo);
    cudaGetSymbolAddress((void**)&hq,   g_hq);
    cudaGetSymbolAddress((void**)&hc,   g_hc);
    cudaGetSymbolAddress((void**)&hqhi, g_hq_hi);
    cudaGetSymbolAddress((void**)&hqlo, g_hq_lo);
    cudaGetSymbolAddress((void**)&hchi, g_hc_hi);
    cudaGetSymbolAddress((void**)&hclo, g_hc_lo);
    cudaGetSymbolAddress((void**)&sq,   g_q);
    cudaGetSymbolAddress((void**)&sk,   g_k);
    cudaGetSymbolAddress((void**)&sv,   g_v);
    cudaGetSymbolAddress((void**)&st2,  g_t2);
    cudaGetSymbolAddress((void**)&sthi, g_st_hi);
    cudaGetSymbolAddress((void**)&stlo, g_st_lo);
    cudaGetSymbolAddress((void**)&ffnhi,g_ffn_hi);
    cudaGetSymbolAddress((void**)&ffnlo,g_ffn_lo);
    cudaGetSymbolAddress((void**)&ssc,  g_sc);
    cudaGetSymbolAddress((void**)&sre,  g_re);

    const size_t D2 = (size_t)DMODEL * DMODEL;
    const size_t DF = (size_t)DMODEL * FFDIM;

    // weight prep: transpose + split to bf16 hi/lo
    for (int l = 0; l < NL; l++) {
        size_t base = (size_t)l * LW;
        wprep_kernel<<<dim3(DMODEL/32, DMODEL/32), 256>>>(Wq + l*D2, whi + base + OFF_Q, wlo + base + OFF_Q, DMODEL, DMODEL);
        wprep_kernel<<<dim3(DMODEL/32, DMODEL/32), 256>>>(Wk + l*D2, whi + base + OFF_K, wlo + base + OFF_K, DMODEL, DMODEL);
        wprep_kernel<<<dim3(DMODEL/32, DMODEL/32), 256>>>(Wv + l*D2, whi + base + OFF_V, wlo + base + OFF_V, DMODEL, DMODEL);
        wprep_kernel<<<dim3(DMODEL/32, DMODEL/32), 256>>>(Wo + l*D2, whi + base + OFF_O, wlo + base + OFF_O, DMODEL, DMODEL);
        wprep_kernel<<<dim3(FFDIM/32,  DMODEL/32), 256>>>(W1 + l*DF, whi + base + OFF_W1, wlo + base + OFF_W1, DMODEL, FFDIM);
        wprep_kernel<<<dim3(DMODEL/32, FFDIM/32),  256>>>(W2 + l*DF, whi + base + OFF_W2, wlo + base + OFF_W2, FFDIM, DMODEL);
    }

    auto encode = [&](const int* ids, const int* mask, int S, float* h,
                      __nv_bfloat16* hhi, __nv_bfloat16* hlo) {
        int rows = BATCH * S;
        int nc = S / CHUNK;
        embed_ln_kernel<<<rows, 256>>>(ids, word_emb, pos_emb, type_emb, eg, eb, h, hhi, hlo, S);
        dim3 gD(DMODEL/128, rows/128);
        dim3 gF(FFDIM/128,  rows/128);
        for (int l = 0; l < NL; l++) {
            size_t wb = (size_t)l * LW;
            mma_gemm<<<gD, 256, SMEMSZ>>>(hhi, hlo, whi + wb + OFF_Q, wlo + wb + OFF_Q,
                bq + l*DMODEL, sq, nullptr, nullptr, rows, DMODEL, DMODEL, 1);
            mma_gemm<<<gD, 256, SMEMSZ>>>(hhi, hlo, whi + wb + OFF_K, wlo + wb + OFF_K,
                bk + l*DMODEL, sk, nullptr, nullptr, rows, DMODEL, DMODEL, 0);
            mma_gemm<<<gD, 256, SMEMSZ>>>(hhi, hlo, whi + wb + OFF_V, wlo + wb + OFF_V,
                bv + l*DMODEL, sv, nullptr, nullptr, rows, DMODEL, DMODEL, 0);
            local_attn_kernel<<<dim3(nc, NHEAD, BATCH), 256>>>(sq, sk, sv, mask, sthi, stlo, nc, S);
            mma_gemm<<<gD, 256, SMEMSZ>>>(sthi, stlo, whi + wb + OFF_O, wlo + wb + OFF_O,
                bo + l*DMODEL, st2, nullptr, nullptr, rows, DMODEL, DMODEL, 0);
            add_ln_kernel<<<rows, 256>>>(h, st2, l1g + l*DMODEL, l1b + l*DMODEL, hhi, hlo);
            mma_gemm<<<gF, 256, SMEMSZ>>>(hhi, hlo, whi + wb + OFF_W1, wlo + wb + OFF_W1,
                b1 + l*FFDIM, nullptr, ffnhi, ffnlo, rows, FFDIM, DMODEL, 2);
            mma_gemm<<<gD, 256, SMEMSZ>>>(ffnhi, ffnlo, whi + wb + OFF_W2, wlo + wb + OFF_W2,
                b2 + l*DMODEL, st2, nullptr, nullptr, rows, DMODEL, FFDIM, 0);
            add_ln_kernel<<<rows, 256>>>(h, st2, l2g + l*DMODEL, l2b + l*DMODEL, hhi, hlo);
        }
    };

    encode(q_ids, q_mask, QLEN, hq, hqhi, hqlo);
    encode(c_ids, c_mask, CLEN, hc, hchi, hclo);

    // interaction: scores[b] = c_h[b] @ q_h[b]^T -> [CLEN, QLEN]
    for (int b = 0; b < BATCH; b++) {
        mma_gemm<<<dim3(QLEN/128, CLEN/128), 256, SMEMSZ>>>(
            hchi + (size_t)b*CLEN*DMODEL, hclo + (size_t)b*CLEN*DMODEL,
            hqhi + (size_t)b*QLEN*DMODEL, hqlo + (size_t)b*QLEN*DMODEL,
            nullptr, ssc + (size_t)b*CLEN*QLEN, nullptr, nullptr,
            CLEN, QLEN, DMODEL, 0);
    }
    softmax_row_kernel<<<BATCH * CLEN, 256>>>(ssc);
    colmax_kernel<<<dim3(BATCH, QLEN/256), 256>>>(ssc, sre);
    fc_kernel<<<1, 32>>>(sre, fcw, fcb, (float*)d_out);
}

// round 4
// speedup vs baseline: 1.4023x; 1.0623x over previous
#include <cuda_runtime.h>
#include <cuda_bf16.h>
#include <math.h>
#include <stdint.h>

// ---------------------------------------------------------------------------
// Problem constants
// ---------------------------------------------------------------------------
#define NL     12
#define DMODEL 768
#define NHEAD  12
#define DHEAD  64
#define FFDIM  3072
#define BATCH  2
#define QLEN   512
#define CLEN   2048
#define CHUNK  256
#define WINW   512
#define NQKV   2304

// ---------------------------------------------------------------------------
// PTX helpers (baseline sm_80+ features only)
// ---------------------------------------------------------------------------
__device__ __forceinline__ uint32_t smem_u32(const void* p) {
    uint32_t a;
    asm("{ .reg .u64 t; cvta.to.shared.u64 t, %1; cvt.u32.u64 %0, t; }" : "=r"(a) : "l"(p));
    return a;
}
__device__ __forceinline__ void ldsm_x4(uint32_t* r, uint32_t addr) {
    asm volatile("ldmatrix.sync.aligned.m8n8.x4.shared.b16 {%0,%1,%2,%3}, [%4];"
                 : "=r"(r[0]), "=r"(r[1]), "=r"(r[2]), "=r"(r[3]) : "r"(addr));
}
__device__ __forceinline__ void mma_bf16(float* c, const uint32_t* a, uint32_t b0, uint32_t b1) {
    asm volatile(
        "mma.sync.aligned.m16n8k16.row.col.f32.bf16.bf16.f32 "
        "{%0,%1,%2,%3}, {%4,%5,%6,%7}, {%8,%9}, {%0,%1,%2,%3};"
        : "+f"(c[0]), "+f"(c[1]), "+f"(c[2]), "+f"(c[3])
        : "r"(a[0]), "r"(a[1]), "r"(a[2]), "r"(a[3]), "r"(b0), "r"(b1));
}
#define CP_ASYNC16(dst, src) \
    asm volatile("cp.async.cg.shared.global [%0], [%1], 16;" :: "r"(dst), "l"(src))
#define CP_COMMIT() asm volatile("cp.async.commit_group;")
#define CP_WAIT(n)  asm volatile("cp.async.wait_group %0;" :: "n"(n))

// ---------------------------------------------------------------------------
// Scratch (device globals)
// ---------------------------------------------------------------------------
#define QKVW (2304ull * 768ull)          // 1769472 per layer
__device__ __nv_bfloat16 g_wqkv_hi[12 * QKVW];
__device__ __nv_bfloat16 g_wqkv_lo[12 * QKVW];
__device__ __nv_bfloat16 g_wo_hi[12 * 589824ull];
__device__ __nv_bfloat16 g_wo_lo[12 * 589824ull];
__device__ __nv_bfloat16 g_w1_hi[12 * 2359296ull];
__device__ __nv_bfloat16 g_w1_lo[12 * 2359296ull];
__device__ __nv_bfloat16 g_w2_hi[12 * 2359296ull];
__device__ __nv_bfloat16 g_w2_lo[12 * 2359296ull];
__device__ float g_bqkv[12 * NQKV];

__device__ float g_hq [BATCH * QLEN * DMODEL];
__device__ float g_hc [BATCH * CLEN * DMODEL];
__device__ __nv_bfloat16 g_hq_hi[BATCH * QLEN * DMODEL];
__device__ __nv_bfloat16 g_hq_lo[BATCH * QLEN * DMODEL];
__device__ __nv_bfloat16 g_hc_hi[BATCH * CLEN * DMODEL];
__device__ __nv_bfloat16 g_hc_lo[BATCH * CLEN * DMODEL];

__device__ float g_qkv[BATCH * CLEN * NQKV];
__device__ float g_t2 [BATCH * CLEN * DMODEL];
__device__ __nv_bfloat16 g_st_hi[BATCH * CLEN * DMODEL];
__device__ __nv_bfloat16 g_st_lo[BATCH * CLEN * DMODEL];
__device__ __nv_bfloat16 g_ffn_hi[BATCH * CLEN * FFDIM];
__device__ __nv_bfloat16 g_ffn_lo[BATCH * CLEN * FFDIM];

__device__ float g_sc [BATCH * CLEN * QLEN];
__device__ float g_re [BATCH * QLEN];

// ---------------------------------------------------------------------------
// Reductions
// ---------------------------------------------------------------------------
__device__ __forceinline__ float block_reduce_sum(float v) {
    __shared__ float sh[33];
    int lane = threadIdx.x & 31, wid = threadIdx.x >> 5;
    #pragma unroll
    for (int o = 16; o; o >>= 1) v += __shfl_xor_sync(0xffffffffu, v, o);
    if (lane == 0) sh[wid] = v;
    __syncthreads();
    if (wid == 0) {
        float t = (lane < 8) ? sh[lane] : 0.f;
        #pragma unroll
        for (int o = 4; o; o >>= 1) t += __shfl_xor_sync(0xffffffffu, t, o);
        if (lane == 0) sh[32] = t;
    }
    __syncthreads();
    float r = sh[32];
    __syncthreads();
    return r;
}
__device__ __forceinline__ float block_reduce_max(float v) {
    __shared__ float sh[33];
    int lane = threadIdx.x & 31, wid = threadIdx.x >> 5;
    #pragma unroll
    for (int o = 16; o; o >>= 1) v = fmaxf(v, __shfl_xor_sync(0xffffffffu, v, o));
    if (lane == 0) sh[wid] = v;
    __syncthreads();
    if (wid == 0) {
        float t = (lane < 8) ? sh[lane] : -1e30f;
        #pragma unroll
        for (int o = 4; o; o >>= 1) t = fmaxf(t, __shfl_xor_sync(0xffffffffu, t, o));
        if (lane == 0) sh[32] = t;
    }
    __syncthreads();
    float r = sh[32];
    __syncthreads();
    return r;
}

__device__ __forceinline__ void split_bf16(float x, __nv_bfloat16& hi, __nv_bfloat16& lo) {
    hi = __float2bfloat16(x);
    lo = __float2bfloat16(x - __bfloat162float(hi));
}

// ---------------------------------------------------------------------------
// Weight transpose + split: W[K,N] -> Thi/Tlo[N,K]
// ---------------------------------------------------------------------------
__global__ void __launch_bounds__(256) wprep_kernel(
    const float* __restrict__ W, __nv_bfloat16* __restrict__ Thi,
    __nv_bfloat16* __restrict__ Tlo, int K, int N)
{
    __shared__ float t[32][33];
    int tx = threadIdx.x & 31, ty = threadIdx.x >> 5;
    int n0 = blockIdx.x * 32, k0 = blockIdx.y * 32;
    #pragma unroll
    for (int j = 0; j < 4; j++)
        t[ty + 8 * j][tx] = W[(size_t)(k0 + ty + 8 * j) * N + n0 + tx];
    __syncthreads();
    #pragma unroll
    for (int j = 0; j < 4; j++) {
        int n = n0 + ty + 8 * j, k = k0 + tx;
        float v = t[tx][ty + 8 * j];
        __nv_bfloat16 hi, lo;
        split_bf16(v, hi, lo);
        Thi[(size_t)n * K + k] = hi;
        Tlo[(size_t)n * K + k] = lo;
    }
}

__global__ void __launch_bounds__(256) biaspack_kernel(
    const float* __restrict__ bq, const float* __restrict__ bk,
    const float* __restrict__ bv, float* __restrict__ out)
{
    int l = blockIdx.x;
    for (int d = threadIdx.x; d < DMODEL; d += 256) {
        out[l * NQKV + d]            = bq[l * DMODEL + d];
        out[l * NQKV + DMODEL + d]   = bk[l * DMODEL + d];
        out[l * NQKV + 2*DMODEL + d] = bv[l * DMODEL + d];
    }
}

// ---------------------------------------------------------------------------
// Embedding + LN / Add + LN
// ---------------------------------------------------------------------------
__global__ void __launch_bounds__(256) embed_ln_kernel(
    const int* __restrict__ ids, const float* __restrict__ we,
    const float* __restrict__ pe, const float* __restrict__ te,
    const float* __restrict__ g, const float* __restrict__ b,
    float* __restrict__ h, __nv_bfloat16* __restrict__ hhi,
    __nv_bfloat16* __restrict__ hlo, int S)
{
    int row = blockIdx.x;
    int s = row % S;
    int tid = threadIdx.x;
    long long id = ids[row];
    const float* w = we + id * DMODEL;
    float x[3];
    #pragma unroll
    for (int l = 0; l < 3; l++) {
        int d = tid + l * 256;
        x[l] = w[d] + pe[(size_t)s * DMODEL + d] + te[d];
    }
    float mean = block_reduce_sum(x[0] + x[1] + x[2]) * (1.f / DMODEL);
    float vs = 0.f;
    #pragma unroll
    for (int l = 0; l < 3; l++) { float dd = x[l] - mean; vs += dd * dd; }
    float rstd = rsqrtf(block_reduce_sum(vs) * (1.f / DMODEL) + 1e-12f);
    size_t base = (size_t)row * DMODEL;
    #pragma unroll
    for (int l = 0; l < 3; l++) {
        int d = tid + l * 256;
        float y = (x[l] - mean) * rstd * g[d] + b[d];
        h[base + d] = y;
        __nv_bfloat16 hi, lo; split_bf16(y, hi, lo);
        hhi[base + d] = hi; hlo[base + d] = lo;
    }
}

__global__ void __launch_bounds__(256) add_ln_kernel(
    float* __restrict__ h, const float* __restrict__ a,
    const float* __restrict__ g, const float* __restrict__ b,
    __nv_bfloat16* __restrict__ hhi, __nv_bfloat16* __restrict__ hlo)
{
    int row = blockIdx.x;
    int tid = threadIdx.x;
    size_t base = (size_t)row * DMODEL;
    float x[3];
    #pragma unroll
    for (int l = 0; l < 3; l++) {
        int d = tid + l * 256;
        x[l] = h[base + d] + a[base + d];
    }
    float mean = block_reduce_sum(x[0] + x[1] + x[2]) * (1.f / DMODEL);
    float vs = 0.f;
    #pragma unroll
    for (int l = 0; l < 3; l++) { float dd = x[l] - mean; vs += dd * dd; }
    float rstd = rsqrtf(block_reduce_sum(vs) * (1.f / DMODEL) + 1e-12f);
    #pragma unroll
    for (int l = 0; l < 3; l++) {
        int d = tid + l * 256;
        float y = (x[l] - mean) * rstd * g[d] + b[d];
        h[base + d] = y;
        __nv_bfloat16 hi, lo; split_bf16(y, hi, lo);
        hhi[base + d] = hi; hlo[base + d] = lo;
    }
}

// ---------------------------------------------------------------------------
// Split-bf16 HMMA GEMM: C[M,N] = A[M,K] @ B[N,K]^T  (3-product Markidis)
// CTA 128x128, BK=32, cp.async double buffer, 8 warps of 32x64, 2 CTAs/SM.
// epi: 0 = bias + fp32; 2 = bias + GELU + bf16 hi/lo; 3 = QKV (bias, *0.125 if col<768)
// ---------------------------------------------------------------------------
#define TILE_B (128 * 40 * 2)          // 10240 bytes per tile (80B padded rows)
#define SMEMSZ (8 * TILE_B)            // 81920

__global__ void __launch_bounds__(256, 2) mma_gemm(
    const __nv_bfloat16* __restrict__ Ahi, const __nv_bfloat16* __restrict__ Alo,
    const __nv_bfloat16* __restrict__ Bhi, const __nv_bfloat16* __restrict__ Blo,
    const float* __restrict__ bias,
    float* __restrict__ Cf, __nv_bfloat16* __restrict__ Chi, __nv_bfloat16* __restrict__ Clo,
    int M, int N, int K, int epi)
{
    extern __shared__ char smem[];
    uint32_t sbase = smem_u32(smem);
    int tid = threadIdx.x, lane = tid & 31, wid = tid >> 5;
    int wm = wid & 3, wn = wid >> 2;             // 4 x 2 warp grid
    int bm = blockIdx.y * 128, bn = blockIdx.x * 128;
    int nkt = K >> 5;

    float acc[2][8][4] = {};

    int lrow = tid >> 2;                          // 0..63
    int lc16 = tid & 3;

    auto load_stage = [&](int buf, int kt) {
        int kb = kt * 32 + lc16 * 8;
        uint32_t dbase = sbase + buf * (4 * TILE_B);
        #pragma unroll
        for (int c = 0; c < 2; c++) {
            int row = lrow + c * 64;
            uint32_t so = (uint32_t)(row * 80 + lc16 * 16);
            CP_ASYNC16(dbase + 0 * TILE_B + so, Ahi + (size_t)(bm + row) * K + kb);
            CP_ASYNC16(dbase + 1 * TILE_B + so, Alo + (size_t)(bm + row) * K + kb);
            CP_ASYNC16(dbase + 2 * TILE_B + so, Bhi + (size_t)(bn + row) * K + kb);
            CP_ASYNC16(dbase + 3 * TILE_B + so, Blo + (size_t)(bn + row) * K + kb);
        }
        CP_COMMIT();
    };

    load_stage(0, 0);

    for (int kt = 0; kt < nkt; kt++) {
        int cur = kt & 1;
        if (kt + 1 < nkt) { load_stage(cur ^ 1, kt + 1); CP_WAIT(1); }
        else              { CP_WAIT(0); }
        __syncthreads();

        uint32_t abase = sbase + cur * (4 * TILE_B);
        #pragma unroll
        for (int ks = 0; ks < 2; ks++) {
            uint32_t koff = (uint32_t)((ks * 16 + (lane >> 4) * 8) * 2);
            // A fragments (hi+lo) for this k-slice
            uint32_t ah[2][4], al[2][4];
            #pragma unroll
            for (int mt = 0; mt < 2; mt++) {
                uint32_t r = abase + (uint32_t)((wm * 32 + mt * 16 + (lane & 15)) * 80) + koff;
                ldsm_x4(ah[mt], r);
                ldsm_x4(al[mt], r + TILE_B);
            }
            // B fragments double-buffered over nt
            uint32_t bh[2][4], bl[2][4];
            {
                uint32_t r = abase + 2 * TILE_B
                           + (uint32_t)((wn * 64 + (lane & 15)) * 80) + koff;
                ldsm_x4(bh[0], r);
                ldsm_x4(bl[0], r + TILE_B);
            }
            #pragma unroll
            for (int nt = 0; nt < 4; nt++) {
                int c = nt & 1;
                if (nt < 3) {
                    uint32_t r = abase + 2 * TILE_B
                               + (uint32_t)((wn * 64 + (nt + 1) * 16 + (lane & 15)) * 80) + koff;
                    ldsm_x4(bh[c ^ 1], r);
                    ldsm_x4(bl[c ^ 1], r + TILE_B);
                }
                #pragma unroll
                for (int mt = 0; mt < 2; mt++) {
                    mma_bf16(acc[mt][nt * 2 + 0], ah[mt], bh[c][0], bh[c][2]);
                    mma_bf16(acc[mt][nt * 2 + 0], ah[mt], bl[c][0], bl[c][2]);
                    mma_bf16(acc[mt][nt * 2 + 0], al[mt], bh[c][0], bh[c][2]);
                    mma_bf16(acc[mt][nt * 2 + 1], ah[mt], bh[c][1], bh[c][3]);
                    mma_bf16(acc[mt][nt * 2 + 1], ah[mt], bl[c][1], bl[c][3]);
                    mma_bf16(acc[mt][nt * 2 + 1], al[mt], bh[c][1], bh[c][3]);
                }
            }
        }
        __syncthreads();
    }

    // epilogue
    int g = lane >> 2, t4 = lane & 3;
    #pragma unroll
    for (int mt = 0; mt < 2; mt++) {
        #pragma unroll
        for (int nt = 0; nt < 4; nt++) {
            #pragma unroll
            for (int h8 = 0; h8 < 2; h8++) {
                float* d = acc[mt][nt * 2 + h8];
                int c0 = bn + wn * 64 + nt * 16 + h8 * 8 + t4 * 2;
                #pragma unroll
                for (int rr = 0; rr < 2; rr++) {
                    int r = bm + wm * 32 + mt * 16 + g + rr * 8;
                    float v0 = d[rr * 2 + 0], v1 = d[rr * 2 + 1];
                    if (bias) { v0 += __ldg(bias + c0); v1 += __ldg(bias + c0 + 1); }
                    if (epi == 3) {
                        if (c0 < DMODEL) { v0 *= 0.125f; v1 *= 0.125f; }
                    } else if (epi == 2) {
                        v0 = 0.5f * v0 * (1.f + erff(v0 * 0.7071067811865476f));
                        v1 = 0.5f * v1 * (1.f + erff(v1 * 0.7071067811865476f));
                        __nv_bfloat16 h0, l0, h1, l1;
                        split_bf16(v0, h0, l0); split_bf16(v1, h1, l1);
                        size_t idx = (size_t)r * N + c0;
                        *(__nv_bfloat162*)&Chi[idx] = __nv_bfloat162(h0, h1);
                        *(__nv_bfloat162*)&Clo[idx] = __nv_bfloat162(l0, l1);
                        continue;
                    }
                    float2 o; o.x = v0; o.y = v1;
                    *(float2*)&Cf[(size_t)r * N + c0] = o;
                }
            }
        }
    }
}

// ---------------------------------------------------------------------------
// Sliding-window attention; reads packed QKV [rows, 2304] fp32
// ---------------------------------------------------------------------------
__global__ void __launch_bounds__(256) local_attn_kernel(
    const float* __restrict__ QKV, const int* __restrict__ mask,
    __nv_bfloat16* __restrict__ Ohi, __nv_bfloat16* __restrict__ Olo,
    int nc, int S)
{
    int n = blockIdx.x, h = blockIdx.y, b = blockIdx.z;
    int i = threadIdx.x;
    int qrow = b * S + n * CHUNK + i;

    const float* qp = QKV + (size_t)qrow * NQKV + h * DHEAD;
    float q[DHEAD];
    #pragma unroll
    for (int d4 = 0; d4 < 16; d4++) {
        float4 t = *(const float4*)(qp + d4 * 4);
        q[d4*4+0] = t.x; q[d4*4+1] = t.y; q[d4*4+2] = t.z; q[d4*4+3] = t.w;
    }

    float m = -1e30f, l = 0.f;
    float acc[DHEAD];
    #pragma unroll
    for (int d = 0; d < DHEAD; d++) acc[d] = 0.f;

    int lane0 = i & ~31;
    int js = lane0;
    int je = min(lane0 + 31 + WINW, 3 * CHUNK - 1);

    for (int j = js; j <= je; j++) {
        int cn = n - 1 + (j >> 8);
        if (cn < 0 || cn >= nc) continue;
        int kpos = cn * CHUNK + (j & 255);
        if (mask[b * S + kpos] == 0) continue;
        if (j < i || j > i + WINW) continue;

        const float* kp = QKV + (size_t)(b * S + kpos) * NQKV + DMODEL + h * DHEAD;
        float s = 0.f;
        #pragma unroll
        for (int d4 = 0; d4 < 16; d4++) {
            float4 kv = *(const float4*)(kp + d4 * 4);
            s += q[d4*4+0]*kv.x + q[d4*4+1]*kv.y + q[d4*4+2]*kv.z + q[d4*4+3]*kv.w;
        }
        float nm = fmaxf(m, s);
        float corr = __expf(m - nm);
        float p = __expf(s - nm);
        l = l * corr + p;
        m = nm;
        const float* vp = kp + DMODEL;   // V block is +768 after K block
        #pragma unroll
        for (int d4 = 0; d4 < 16; d4++) {
            float4 vv = *(const float4*)(vp + d4 * 4);
            acc[d4*4+0] = acc[d4*4+0]*corr + p*vv.x;
            acc[d4*4+1] = acc[d4*4+1]*corr + p*vv.y;
            acc[d4*4+2] = acc[d4*4+2]*corr + p*vv.z;
            acc[d4*4+3] = acc[d4*4+3]*corr + p*vv.w;
        }
    }
    float inv = 1.f / l;
    size_t ob = (size_t)qrow * DMODEL + h * DHEAD;
    #pragma unroll
    for (int d = 0; d < DHEAD; d++) {
        float val = acc[d] * inv;
        __nv_bfloat16 hi, lo; split_bf16(val, hi, lo);
        Ohi[ob + d] = hi; Olo[ob + d] = lo;
    }
}

// ---------------------------------------------------------------------------
// Interaction head
// ---------------------------------------------------------------------------
__global__ void __launch_bounds__(256) softmax_row_kernel(float* __restrict__ P)
{
    int row = blockIdx.x, tid = threadIdx.x;
    float* p = P + (size_t)row * QLEN;
    float x0 = p[tid], x1 = p[tid + 256];
    float m = block_reduce_max(fmaxf(x0, x1));
    float e0 = __expf(x0 - m), e1 = __expf(x1 - m);
    float s = block_reduce_sum(e0 + e1);
    float inv = 1.f / s;
    p[tid] = e0 * inv;
    p[tid + 256] = e1 * inv;
}

__global__ void __launch_bounds__(256) colmax_kernel(
    const float* __restrict__ P, float* __restrict__ re)
{
    int b = blockIdx.x;
    int q = blockIdx.y * 256 + threadIdx.x;
    const float* p = P + (size_t)b * CLEN * QLEN + q;
    float m = -1e30f;
    for (int r = 0; r < CLEN; r++) m = fmaxf(m, p[(size_t)r * QLEN]);
    re[b * QLEN + q] = m;
}

__global__ void fc_kernel(const float* __restrict__ re, const float* __restrict__ w,
                          const float* __restrict__ bfc, float* __restrict__ out)
{
    int t = threadIdx.x;
    if (t >= 8) return;
    int b = t >> 2, o = t & 3;
    float s = bfc[o];
    for (int q = 0; q < QLEN; q++) s += re[b * QLEN + q] * w[q * 4 + o];
    out[b * 4 + o] = s;
}

// ---------------------------------------------------------------------------
// Host orchestration
// ---------------------------------------------------------------------------
extern "C" void kernel_launch(void* const* d_in, const int* in_sizes, int n_in,
                              void* d_out, int out_size)
{
    const int*   q_ids    = (const int*)  d_in[0];
    const int*   c_ids    = (const int*)  d_in[1];
    const int*   q_mask   = (const int*)  d_in[2];
    const int*   c_mask   = (const int*)  d_in[3];
    const float* word_emb = (const float*)d_in[4];
    const float* pos_emb  = (const float*)d_in[5];
    const float* type_emb = (const float*)d_in[6];
    const float* eg       = (const float*)d_in[7];
    const float* eb       = (const float*)d_in[8];
    const float* Wq  = (const float*)d_in[9];
    const float* bq  = (const float*)d_in[10];
    const float* Wk  = (const float*)d_in[11];
    const float* bk  = (const float*)d_in[12];
    const float* Wv  = (const float*)d_in[13];
    const float* bv  = (const float*)d_in[14];
    const float* Wo  = (const float*)d_in[15];
    const float* bo  = (const float*)d_in[16];
    const float* l1g = (const float*)d_in[17];
    const float* l1b = (const float*)d_in[18];
    const float* W1  = (const float*)d_in[19];
    const float* b1  = (const float*)d_in[20];
    const float* W2  = (const float*)d_in[21];
    const float* b2  = (const float*)d_in[22];
    const float* l2g = (const float*)d_in[23];
    const float* l2b = (const float*)d_in[24];
    const float* fcw = (const float*)d_in[25];
    const float* fcb = (const float*)d_in[26];

    cudaFuncSetAttribute(mma_gemm, cudaFuncAttributeMaxDynamicSharedMemorySize, SMEMSZ);

    __nv_bfloat16 *wqkvhi, *wqkvlo, *wohi, *wolo, *w1hi, *w1lo, *w2hi, *w2lo;
    __nv_bfloat16 *hqhi, *hqlo, *hchi, *hclo, *sthi, *stlo, *ffnhi, *ffnlo;
    float *bqkv, *hq, *hc, *qkv, *st2, *ssc, *sre;
    cudaGetSymbolAddress((void**)&wqkvhi, g_wqkv_hi);
    cudaGetSymbolAddress((void**)&wqkvlo, g_wqkv_lo);
    cudaGetSymbolAddress((void**)&wohi,   g_wo_hi);
    cudaGetSymbolAddress((void**)&wolo,   g_wo_lo);
    cudaGetSymbolAddress((void**)&w1hi,   g_w1_hi);
    cudaGetSymbolAddress((void**)&w1lo,   g_w1_lo);
    cudaGetSymbolAddress((void**)&w2hi,   g_w2_hi);
    cudaGetSymbolAddress((void**)&w2lo,   g_w2_lo);
    cudaGetSymbolAddress((void**)&bqkv,   g_bqkv);
    cudaGetSymbolAddress((void**)&hq,     g_hq);
    cudaGetSymbolAddress((void**)&hc,     g_hc);
    cudaGetSymbolAddress((void**)&hqhi,   g_hq_hi);
    cudaGetSymbolAddress((void**)&hqlo,   g_hq_lo);
    cudaGetSymbolAddress((void**)&hchi,   g_hc_hi);
    cudaGetSymbolAddress((void**)&hclo,   g_hc_lo);
    cudaGetSymbolAddress((void**)&qkv,    g_qkv);
    cudaGetSymbolAddress((void**)&st2,    g_t2);
    cudaGetSymbolAddress((void**)&sthi,   g_st_hi);
    cudaGetSymbolAddress((void**)&stlo,   g_st_lo);
    cudaGetSymbolAddress((void**)&ffnhi,  g_ffn_hi);
    cudaGetSymbolAddress((void**)&ffnlo,  g_ffn_lo);
    cudaGetSymbolAddress((void**)&ssc,    g_sc);
    cudaGetSymbolAddress((void**)&sre,    g_re);

    const size_t D2 = (size_t)DMODEL * DMODEL;
    const size_t DF = (size_t)DMODEL * FFDIM;

    dim3 gw(DMODEL/32, DMODEL/32);

    // --- launches 0-2: layer-0 QKV weight prep ---
    wprep_kernel<<<gw, 256>>>(Wq, wqkvhi + 0,       wqkvlo + 0,       DMODEL, DMODEL);
    wprep_kernel<<<gw, 256>>>(Wk, wqkvhi + 589824,  wqkvlo + 589824,  DMODEL, DMODEL);
    wprep_kernel<<<gw, 256>>>(Wv, wqkvhi + 1179648, wqkvlo + 1179648, DMODEL, DMODEL);
    // --- launch 3: bias pack ---
    biaspack_kernel<<<12, 256>>>(bq, bk, bv, bqkv);
    // --- launch 4: c-path embedding ---
    embed_ln_kernel<<<BATCH*CLEN, 256>>>(c_ids, word_emb, pos_emb, type_emb, eg, eb,
                                         hc, hchi, hclo, CLEN);
    // --- launch 5: c-path layer-0 QKV GEMM  (ncu -s 5 profiles THIS) ---
    mma_gemm<<<dim3(NQKV/128, (BATCH*CLEN)/128), 256, SMEMSZ>>>(
        hchi, hclo, wqkvhi, wqkvlo, bqkv, qkv, nullptr, nullptr,
        BATCH*CLEN, NQKV, DMODEL, 3);

    // --- remaining weight prep ---
    wprep_kernel<<<gw, 256>>>(Wo, wohi, wolo, DMODEL, DMODEL);
    wprep_kernel<<<dim3(FFDIM/32, DMODEL/32), 256>>>(W1, w1hi, w1lo, DMODEL, FFDIM);
    wprep_kernel<<<dim3(DMODEL/32, FFDIM/32), 256>>>(W2, w2hi, w2lo, FFDIM, DMODEL);
    for (int l = 1; l < NL; l++) {
        size_t qb = (size_t)l * QKVW;
        wprep_kernel<<<gw, 256>>>(Wq + l*D2, wqkvhi + qb,           wqkvlo + qb,           DMODEL, DMODEL);
        wprep_kernel<<<gw, 256>>>(Wk + l*D2, wqkvhi + qb + 589824,  wqkvlo + qb + 589824,  DMODEL, DMODEL);
        wprep_kernel<<<gw, 256>>>(Wv + l*D2, wqkvhi + qb + 1179648, wqkvlo + qb + 1179648, DMODEL, DMODEL);
        wprep_kernel<<<gw, 256>>>(Wo + l*D2, wohi + l*589824ull, wolo + l*589824ull, DMODEL, DMODEL);
        wprep_kernel<<<dim3(FFDIM/32, DMODEL/32), 256>>>(W1 + l*DF, w1hi + l*2359296ull, w1lo + l*2359296ull, DMODEL, FFDIM);
        wprep_kernel<<<dim3(DMODEL/32, FFDIM/32), 256>>>(W2 + l*DF, w2hi + l*2359296ull, w2lo + l*2359296ull, FFDIM, DMODEL);
    }
    // q-path embedding
    embed_ln_kernel<<<BATCH*QLEN, 256>>>(q_ids, word_emb, pos_emb, type_emb, eg, eb,
                                         hq, hqhi, hqlo, QLEN);

    auto encode = [&](const int* mask, int S, float* h,
                      __nv_bfloat16* hhi, __nv_bfloat16* hlo, bool qkv0_done) {
        int rows = BATCH * S;
        int nc = S / CHUNK;
        dim3 gQKV(NQKV/128, rows/128);
        dim3 gD(DMODEL/128, rows/128);
        dim3 gF(FFDIM/128,  rows/128);
        for (int l = 0; l < NL; l++) {
            size_t qb = (size_t)l * QKVW;
            if (!(l == 0 && qkv0_done)) {
                mma_gemm<<<gQKV, 256, SMEMSZ>>>(hhi, hlo, wqkvhi + qb, wqkvlo + qb,
                    bqkv + l*NQKV, qkv, nullptr, nullptr, rows, NQKV, DMODEL, 3);
            }
            local_attn_kernel<<<dim3(nc, NHEAD, BATCH), 256>>>(qkv, mask, sthi, stlo, nc, S);
            mma_gemm<<<gD, 256, SMEMSZ>>>(sthi, stlo, wohi + l*589824ull, wolo + l*589824ull,
                bo + l*DMODEL, st2, nullptr, nullptr, rows, DMODEL, DMODEL, 0);
            add_ln_kernel<<<rows, 256>>>(h, st2, l1g + l*DMODEL, l1b + l*DMODEL, hhi, hlo);
            mma_gemm<<<gF, 256, SMEMSZ>>>(hhi, hlo, w1hi + l*2359296ull, w1lo + l*2359296ull,
                b1 + l*FFDIM, nullptr, ffnhi, ffnlo, rows, FFDIM, DMODEL, 2);
            mma_gemm<<<gD, 256, SMEMSZ>>>(ffnhi, ffnlo, w2hi + l*2359296ull, w2lo + l*2359296ull,
                b2 + l*DMODEL, st2, nullptr, nullptr, rows, DMODEL, FFDIM, 0);
            add_ln_kernel<<<rows, 256>>>(h, st2, l2g + l*DMODEL, l2b + l*DMODEL, hhi, hlo);
        }
    };

    encode(c_mask, CLEN, hc, hchi, hclo, true);   // c path (layer-0 QKV already done)
    encode(q_mask, QLEN, hq, hqhi, hqlo, false);  // q path

    // interaction: scores[b] = c_h[b] @ q_h[b]^T -> [CLEN, QLEN]
    for (int b = 0; b < BATCH; b++) {
        mma_gemm<<<dim3(QLEN/128, CLEN/128), 256, SMEMSZ>>>(
            hchi + (size_t)b*CLEN*DMODEL, hclo + (size_t)b*CLEN*DMODEL,
            hqhi + (size_t)b*QLEN*DMODEL, hqlo + (size_t)b*QLEN*DMODEL,
            nullptr, ssc + (size_t)b*CLEN*QLEN, nullptr, nullptr,
            CLEN, QLEN, DMODEL, 0);
    }
    softmax_row_kernel<<<BATCH * CLEN, 256>>>(ssc);
    colmax_kernel<<<dim3(BATCH, QLEN/256), 256>>>(ssc, sre);
    fc_kernel<<<1, 32>>>(sre, fcw, fcb, (float*)d_out);
}

// round 5
// speedup vs baseline: 1.5120x; 1.0782x over previous
#include <cuda_runtime.h>
#include <cuda_bf16.h>
#include <math.h>
#include <stdint.h>

// ---------------------------------------------------------------------------
// Problem constants
// ---------------------------------------------------------------------------
#define NL     12
#define DMODEL 768
#define NHEAD  12
#define DHEAD  64
#define FFDIM  3072
#define BATCH  2
#define QLEN   512
#define CLEN   2048
#define CHUNK  256
#define WINW   512
#define NQKV   2304
#define CROWS  (BATCH * CLEN)              // 4096
#define QROWS  (BATCH * QLEN)              // 1024
#define ROWSA  (CROWS + QROWS)             // 5120 merged rows
#define QBASE  CROWS                       // q rows start here

// ---------------------------------------------------------------------------
// PTX helpers (baseline sm_80+ features only)
// ---------------------------------------------------------------------------
__device__ __forceinline__ uint32_t smem_u32(const void* p) {
    uint32_t a;
    asm("{ .reg .u64 t; cvta.to.shared.u64 t, %1; cvt.u32.u64 %0, t; }" : "=r"(a) : "l"(p));
    return a;
}
__device__ __forceinline__ void ldsm_x4(uint32_t* r, uint32_t addr) {
    asm volatile("ldmatrix.sync.aligned.m8n8.x4.shared.b16 {%0,%1,%2,%3}, [%4];"
                 : "=r"(r[0]), "=r"(r[1]), "=r"(r[2]), "=r"(r[3]) : "r"(addr));
}
__device__ __forceinline__ void mma_bf16(float* c, const uint32_t* a, uint32_t b0, uint32_t b1) {
    asm volatile(
        "mma.sync.aligned.m16n8k16.row.col.f32.bf16.bf16.f32 "
        "{%0,%1,%2,%3}, {%4,%5,%6,%7}, {%8,%9}, {%0,%1,%2,%3};"
        : "+f"(c[0]), "+f"(c[1]), "+f"(c[2]), "+f"(c[3])
        : "r"(a[0]), "r"(a[1]), "r"(a[2]), "r"(a[3]), "r"(b0), "r"(b1));
}
#define CP_ASYNC16(dst, src) \
    asm volatile("cp.async.cg.shared.global [%0], [%1], 16;" :: "r"(dst), "l"(src))
#define CP_COMMIT() asm volatile("cp.async.commit_group;")
#define CP_WAIT(n)  asm volatile("cp.async.wait_group %0;" :: "n"(n))

// ---------------------------------------------------------------------------
// Scratch (device globals)
// ---------------------------------------------------------------------------
#define D2   ((size_t)DMODEL * DMODEL)     // 589824
#define DF   ((size_t)DMODEL * FFDIM)      // 2359296
#define QKVW (3ull * D2)                   // 1769472 per layer

__device__ __nv_bfloat16 g_wqkv_hi[12 * QKVW];
__device__ __nv_bfloat16 g_wqkv_lo[12 * QKVW];
__device__ __nv_bfloat16 g_wo_hi[12 * D2];
__device__ __nv_bfloat16 g_wo_lo[12 * D2];
__device__ __nv_bfloat16 g_w1_hi[12 * DF];
__device__ __nv_bfloat16 g_w1_lo[12 * DF];
__device__ __nv_bfloat16 g_w2_hi[12 * DF];
__device__ __nv_bfloat16 g_w2_lo[12 * DF];

__device__ float g_h [ROWSA * DMODEL];
__device__ __nv_bfloat16 g_h_hi[ROWSA * DMODEL];
__device__ __nv_bfloat16 g_h_lo[ROWSA * DMODEL];
__device__ float g_qkv[ROWSA * NQKV];
__device__ float g_t2 [ROWSA * DMODEL];
__device__ __nv_bfloat16 g_st_hi[ROWSA * DMODEL];
__device__ __nv_bfloat16 g_st_lo[ROWSA * DMODEL];
__device__ __nv_bfloat16 g_ffn_hi[ROWSA * FFDIM];
__device__ __nv_bfloat16 g_ffn_lo[ROWSA * FFDIM];

__device__ float g_sc [BATCH * CLEN * QLEN];
__device__ float g_re [BATCH * QLEN];

// ---------------------------------------------------------------------------
// Reductions
// ---------------------------------------------------------------------------
__device__ __forceinline__ float block_reduce_sum(float v) {
    __shared__ float sh[33];
    int lane = threadIdx.x & 31, wid = threadIdx.x >> 5;
    #pragma unroll
    for (int o = 16; o; o >>= 1) v += __shfl_xor_sync(0xffffffffu, v, o);
    if (lane == 0) sh[wid] = v;
    __syncthreads();
    if (wid == 0) {
        float t = (lane < 8) ? sh[lane] : 0.f;
        #pragma unroll
        for (int o = 4; o; o >>= 1) t += __shfl_xor_sync(0xffffffffu, t, o);
        if (lane == 0) sh[32] = t;
    }
    __syncthreads();
    float r = sh[32];
    __syncthreads();
    return r;
}
__device__ __forceinline__ float block_reduce_max(float v) {
    __shared__ float sh[33];
    int lane = threadIdx.x & 31, wid = threadIdx.x >> 5;
    #pragma unroll
    for (int o = 16; o; o >>= 1) v = fmaxf(v, __shfl_xor_sync(0xffffffffu, v, o));
    if (lane == 0) sh[wid] = v;
    __syncthreads();
    if (wid == 0) {
        float t = (lane < 8) ? sh[lane] : -1e30f;
        #pragma unroll
        for (int o = 4; o; o >>= 1) t = fmaxf(t, __shfl_xor_sync(0xffffffffu, t, o));
        if (lane == 0) sh[32] = t;
    }
    __syncthreads();
    float r = sh[32];
    __syncthreads();
    return r;
}

__device__ __forceinline__ void split_bf16(float x, __nv_bfloat16& hi, __nv_bfloat16& lo) {
    hi = __float2bfloat16(x);
    lo = __float2bfloat16(x - __bfloat162float(hi));
}

// ---------------------------------------------------------------------------
// Batched weight transpose + split
// ---------------------------------------------------------------------------
// QKV: all 12 layers x {Wq,Wk,Wv} in one launch. grid (24, 24, 36)
__global__ void __launch_bounds__(256) wprep_qkv_all(
    const float* __restrict__ Wq, const float* __restrict__ Wk,
    const float* __restrict__ Wv,
    __nv_bfloat16* __restrict__ Thi, __nv_bfloat16* __restrict__ Tlo)
{
    __shared__ float t[32][33];
    int z = blockIdx.z;
    int l = z / 3, which = z % 3;
    const float* W = (which == 0 ? Wq : (which == 1 ? Wk : Wv)) + (size_t)l * D2;
    __nv_bfloat16* ohi = Thi + (size_t)l * QKVW + (size_t)which * D2;
    __nv_bfloat16* olo = Tlo + (size_t)l * QKVW + (size_t)which * D2;
    int tx = threadIdx.x & 31, ty = threadIdx.x >> 5;
    int n0 = blockIdx.x * 32, k0 = blockIdx.y * 32;
    #pragma unroll
    for (int j = 0; j < 4; j++)
        t[ty + 8 * j][tx] = W[(size_t)(k0 + ty + 8 * j) * DMODEL + n0 + tx];
    __syncthreads();
    #pragma unroll
    for (int j = 0; j < 4; j++) {
        int n = n0 + ty + 8 * j, k = k0 + tx;
        __nv_bfloat16 hi, lo;
        split_bf16(t[tx][ty + 8 * j], hi, lo);
        ohi[(size_t)n * DMODEL + k] = hi;
        olo[(size_t)n * DMODEL + k] = lo;
    }
}

// Generic batched: W[K,N] per layer (stride sW) -> T[N,K] (stride sT). grid (N/32, K/32, NL)
__global__ void __launch_bounds__(256) wprep_b(
    const float* __restrict__ W, __nv_bfloat16* __restrict__ Thi,
    __nv_bfloat16* __restrict__ Tlo, int K, int N)
{
    __shared__ float t[32][33];
    size_t l = blockIdx.z;
    const float* Wl = W + l * (size_t)K * N;
    __nv_bfloat16* ohi = Thi + l * (size_t)K * N;
    __nv_bfloat16* olo = Tlo + l * (size_t)K * N;
    int tx = threadIdx.x & 31, ty = threadIdx.x >> 5;
    int n0 = blockIdx.x * 32, k0 = blockIdx.y * 32;
    #pragma unroll
    for (int j = 0; j < 4; j++)
        t[ty + 8 * j][tx] = Wl[(size_t)(k0 + ty + 8 * j) * N + n0 + tx];
    __syncthreads();
    #pragma unroll
    for (int j = 0; j < 4; j++) {
        int n = n0 + ty + 8 * j, k = k0 + tx;
        __nv_bfloat16 hi, lo;
        split_bf16(t[tx][ty + 8 * j], hi, lo);
        ohi[(size_t)n * K + k] = hi;
        olo[(size_t)n * K + k] = lo;
    }
}

// ---------------------------------------------------------------------------
// Embedding + LN / Add + LN (merged-row layout)
// ---------------------------------------------------------------------------
__global__ void __launch_bounds__(256) embed_ln_kernel(
    const int* __restrict__ ids, const float* __restrict__ we,
    const float* __restrict__ pe, const float* __restrict__ te,
    const float* __restrict__ g, const float* __restrict__ b,
    float* __restrict__ h, __nv_bfloat16* __restrict__ hhi,
    __nv_bfloat16* __restrict__ hlo, int S, int row_off)
{
    int rlocal = blockIdx.x;
    int s = rlocal % S;
    int tid = threadIdx.x;
    long long id = ids[rlocal];
    const float* w = we + id * DMODEL;
    float x[3];
    #pragma unroll
    for (int l = 0; l < 3; l++) {
        int d = tid + l * 256;
        x[l] = w[d] + pe[(size_t)s * DMODEL + d] + te[d];
    }
    float mean = block_reduce_sum(x[0] + x[1] + x[2]) * (1.f / DMODEL);
    float vs = 0.f;
    #pragma unroll
    for (int l = 0; l < 3; l++) { float dd = x[l] - mean; vs += dd * dd; }
    float rstd = rsqrtf(block_reduce_sum(vs) * (1.f / DMODEL) + 1e-12f);
    size_t base = (size_t)(row_off + rlocal) * DMODEL;
    #pragma unroll
    for (int l = 0; l < 3; l++) {
        int d = tid + l * 256;
        float y = (x[l] - mean) * rstd * g[d] + b[d];
        h[base + d] = y;
        __nv_bfloat16 hi, lo; split_bf16(y, hi, lo);
        hhi[base + d] = hi; hlo[base + d] = lo;
    }
}

__global__ void __launch_bounds__(256) add_ln_kernel(
    float* __restrict__ h, const float* __restrict__ a,
    const float* __restrict__ g, const float* __restrict__ b,
    __nv_bfloat16* __restrict__ hhi, __nv_bfloat16* __restrict__ hlo)
{
    int row = blockIdx.x;
    int tid = threadIdx.x;
    size_t base = (size_t)row * DMODEL;
    float x[3];
    #pragma unroll
    for (int l = 0; l < 3; l++) {
        int d = tid + l * 256;
        x[l] = h[base + d] + a[base + d];
    }
    float mean = block_reduce_sum(x[0] + x[1] + x[2]) * (1.f / DMODEL);
    float vs = 0.f;
    #pragma unroll
    for (int l = 0; l < 3; l++) { float dd = x[l] - mean; vs += dd * dd; }
    float rstd = rsqrtf(block_reduce_sum(vs) * (1.f / DMODEL) + 1e-12f);
    #pragma unroll
    for (int l = 0; l < 3; l++) {
        int d = tid + l * 256;
        float y = (x[l] - mean) * rstd * g[d] + b[d];
        h[base + d] = y;
        __nv_bfloat16 hi, lo; split_bf16(y, hi, lo);
        hhi[base + d] = hi; hlo[base + d] = lo;
    }
}

// ---------------------------------------------------------------------------
// Split-bf16 HMMA GEMM: C[M,N] = A[M,K] @ B[N,K]^T  (3-product Markidis)
// CTA 128x128, BK=32, cp.async double buffer, 8 warps of 32x64, 2 CTAs/SM.
// epi: 0 = bias + fp32; 2 = bias + GELU + bf16 hi/lo;
//      3 = QKV: bias from {b1,b2,b3} by column range, *0.125 on q columns
// ---------------------------------------------------------------------------
#define TILE_B (128 * 40 * 2)          // 10240 bytes per tile (80B padded rows)
#define SMEMSZ (8 * TILE_B)            // 81920

__global__ void __launch_bounds__(256, 2) mma_gemm(
    const __nv_bfloat16* __restrict__ Ahi, const __nv_bfloat16* __restrict__ Alo,
    const __nv_bfloat16* __restrict__ Bhi, const __nv_bfloat16* __restrict__ Blo,
    const float* __restrict__ bias, const float* __restrict__ bias2,
    const float* __restrict__ bias3,
    float* __restrict__ Cf, __nv_bfloat16* __restrict__ Chi, __nv_bfloat16* __restrict__ Clo,
    int M, int N, int K, int epi)
{
    extern __shared__ char smem[];
    uint32_t sbase = smem_u32(smem);
    int tid = threadIdx.x, lane = tid & 31, wid = tid >> 5;
    int wm = wid & 3, wn = wid >> 2;             // 4 x 2 warp grid
    int bm = blockIdx.y * 128, bn = blockIdx.x * 128;
    int nkt = K >> 5;

    float acc[2][8][4] = {};

    int lrow = tid >> 2;                          // 0..63
    int lc16 = tid & 3;

    auto load_stage = [&](int buf, int kt) {
        int kb = kt * 32 + lc16 * 8;
        uint32_t dbase = sbase + buf * (4 * TILE_B);
        #pragma unroll
        for (int c = 0; c < 2; c++) {
            int row = lrow + c * 64;
            uint32_t so = (uint32_t)(row * 80 + lc16 * 16);
            CP_ASYNC16(dbase + 0 * TILE_B + so, Ahi + (size_t)(bm + row) * K + kb);
            CP_ASYNC16(dbase + 1 * TILE_B + so, Alo + (size_t)(bm + row) * K + kb);
            CP_ASYNC16(dbase + 2 * TILE_B + so, Bhi + (size_t)(bn + row) * K + kb);
            CP_ASYNC16(dbase + 3 * TILE_B + so, Blo + (size_t)(bn + row) * K + kb);
        }
        CP_COMMIT();
    };

    load_stage(0, 0);

    for (int kt = 0; kt < nkt; kt++) {
        int cur = kt & 1;
        if (kt + 1 < nkt) { load_stage(cur ^ 1, kt + 1); CP_WAIT(1); }
        else              { CP_WAIT(0); }
        __syncthreads();

        uint32_t abase = sbase + cur * (4 * TILE_B);
        #pragma unroll
        for (int ks = 0; ks < 2; ks++) {
            uint32_t koff = (uint32_t)((ks * 16 + (lane >> 4) * 8) * 2);
            uint32_t ah[2][4], al[2][4];
            #pragma unroll
            for (int mt = 0; mt < 2; mt++) {
                uint32_t r = abase + (uint32_t)((wm * 32 + mt * 16 + (lane & 15)) * 80) + koff;
                ldsm_x4(ah[mt], r);
                ldsm_x4(al[mt], r + TILE_B);
            }
            uint32_t bh[2][4], bl[2][4];
            {
                uint32_t r = abase + 2 * TILE_B
                           + (uint32_t)((wn * 64 + (lane & 15)) * 80) + koff;
                ldsm_x4(bh[0], r);
                ldsm_x4(bl[0], r + TILE_B);
            }
            #pragma unroll
            for (int nt = 0; nt < 4; nt++) {
                int c = nt & 1;
                if (nt < 3) {
                    uint32_t r = abase + 2 * TILE_B
                               + (uint32_t)((wn * 64 + (nt + 1) * 16 + (lane & 15)) * 80) + koff;
                    ldsm_x4(bh[c ^ 1], r);
                    ldsm_x4(bl[c ^ 1], r + TILE_B);
                }
                #pragma unroll
                for (int mt = 0; mt < 2; mt++) {
                    mma_bf16(acc[mt][nt * 2 + 0], ah[mt], bh[c][0], bh[c][2]);
                    mma_bf16(acc[mt][nt * 2 + 0], ah[mt], bl[c][0], bl[c][2]);
                    mma_bf16(acc[mt][nt * 2 + 0], al[mt], bh[c][0], bh[c][2]);
                    mma_bf16(acc[mt][nt * 2 + 1], ah[mt], bh[c][1], bh[c][3]);
                    mma_bf16(acc[mt][nt * 2 + 1], ah[mt], bl[c][1], bl[c][3]);
                    mma_bf16(acc[mt][nt * 2 + 1], al[mt], bh[c][1], bh[c][3]);
                }
            }
        }
        __syncthreads();
    }

    // epilogue
    int g = lane >> 2, t4 = lane & 3;
    #pragma unroll
    for (int mt = 0; mt < 2; mt++) {
        #pragma unroll
        for (int nt = 0; nt < 4; nt++) {
            #pragma unroll
            for (int h8 = 0; h8 < 2; h8++) {
                float* d = acc[mt][nt * 2 + h8];
                int c0 = bn + wn * 64 + nt * 16 + h8 * 8 + t4 * 2;
                #pragma unroll
                for (int rr = 0; rr < 2; rr++) {
                    int r = bm + wm * 32 + mt * 16 + g + rr * 8;
                    float v0 = d[rr * 2 + 0], v1 = d[rr * 2 + 1];
                    if (epi == 3) {
                        if (c0 < DMODEL) {
                            v0 = (v0 + __ldg(bias + c0)) * 0.125f;
                            v1 = (v1 + __ldg(bias + c0 + 1)) * 0.125f;
                        } else if (c0 < 2 * DMODEL) {
                            v0 += __ldg(bias2 + c0 - DMODEL);
                            v1 += __ldg(bias2 + c0 + 1 - DMODEL);
                        } else {
                            v0 += __ldg(bias3 + c0 - 2 * DMODEL);
                            v1 += __ldg(bias3 + c0 + 1 - 2 * DMODEL);
                        }
                    } else if (bias) {
                        v0 += __ldg(bias + c0);
                        v1 += __ldg(bias + c0 + 1);
                    }
                    if (epi == 2) {
                        v0 = 0.5f * v0 * (1.f + erff(v0 * 0.7071067811865476f));
                        v1 = 0.5f * v1 * (1.f + erff(v1 * 0.7071067811865476f));
                        __nv_bfloat16 h0, l0, h1, l1;
                        split_bf16(v0, h0, l0); split_bf16(v1, h1, l1);
                        size_t idx = (size_t)r * N + c0;
                        *(__nv_bfloat162*)&Chi[idx] = __nv_bfloat162(h0, h1);
                        *(__nv_bfloat162*)&Clo[idx] = __nv_bfloat162(l0, l1);
                        continue;
                    }
                    float2 o; o.x = v0; o.y = v1;
                    *(float2*)&Cf[(size_t)r * N + c0] = o;
                }
            }
        }
    }
}

// ---------------------------------------------------------------------------
// Sliding-window attention; reads packed QKV [merged rows, 2304] fp32.
// Online softmax with rescale-on-new-max; 4-way split dot chains.
// ---------------------------------------------------------------------------
__global__ void __launch_bounds__(256) local_attn_kernel(
    const float* __restrict__ QKV, const int* __restrict__ mask,
    __nv_bfloat16* __restrict__ Ohi, __nv_bfloat16* __restrict__ Olo,
    int nc, int S, int row_base)
{
    int n = blockIdx.x, h = blockIdx.y, b = blockIdx.z;
    int i = threadIdx.x;
    int qrow = row_base + b * S + n * CHUNK + i;

    const float* qp = QKV + (size_t)qrow * NQKV + h * DHEAD;
    float q[DHEAD];
    #pragma unroll
    for (int d4 = 0; d4 < 16; d4++) {
        float4 t = *(const float4*)(qp + d4 * 4);
        q[d4*4+0] = t.x; q[d4*4+1] = t.y; q[d4*4+2] = t.z; q[d4*4+3] = t.w;
    }

    float m = -1e30f, l = 0.f;
    float acc[DHEAD];
    #pragma unroll
    for (int d = 0; d < DHEAD; d++) acc[d] = 0.f;

    int lane0 = i & ~31;
    int js = lane0;
    int je = min(lane0 + 31 + WINW, 3 * CHUNK - 1);

    for (int j = js; j <= je; j++) {
        int cn = n - 1 + (j >> 8);
        if (cn < 0 || cn >= nc) continue;                 // warp-uniform
        int kpos = cn * CHUNK + (j & 255);
        if (mask[b * S + kpos] == 0) continue;            // warp-uniform
        if (j < i || j > i + WINW) continue;              // per-lane band

        const float* kp = QKV + (size_t)(row_base + b * S + kpos) * NQKV + DMODEL + h * DHEAD;
        float s0 = 0.f, s1 = 0.f, s2 = 0.f, s3 = 0.f;
        #pragma unroll
        for (int d4 = 0; d4 < 16; d4++) {
            float4 kv = *(const float4*)(kp + d4 * 4);
            s0 += q[d4*4+0] * kv.x;
            s1 += q[d4*4+1] * kv.y;
            s2 += q[d4*4+2] * kv.z;
            s3 += q[d4*4+3] * kv.w;
        }
        float s = (s0 + s1) + (s2 + s3);

        if (s > m) {                       // rare after warmup
            float corr = __expf(m - s);
            l *= corr;
            #pragma unroll
            for (int d = 0; d < DHEAD; d++) acc[d] *= corr;
            m = s;
        }
        float p = __expf(s - m);
        l += p;
        const float* vp = kp + DMODEL;
        #pragma unroll
        for (int d4 = 0; d4 < 16; d4++) {
            float4 vv = *(const float4*)(vp + d4 * 4);
            acc[d4*4+0] += p * vv.x;
            acc[d4*4+1] += p * vv.y;
            acc[d4*4+2] += p * vv.z;
            acc[d4*4+3] += p * vv.w;
        }
    }
    float inv = 1.f / l;
    size_t ob = (size_t)qrow * DMODEL + h * DHEAD;
    #pragma unroll
    for (int d = 0; d < DHEAD; d += 2) {
        float v0 = acc[d] * inv, v1 = acc[d+1] * inv;
        __nv_bfloat16 h0, l0, h1, l1;
        split_bf16(v0, h0, l0); split_bf16(v1, h1, l1);
        *(__nv_bfloat162*)&Ohi[ob + d] = __nv_bfloat162(h0, h1);
        *(__nv_bfloat162*)&Olo[ob + d] = __nv_bfloat162(l0, l1);
    }
}

// ---------------------------------------------------------------------------
// Interaction head
// ---------------------------------------------------------------------------
__global__ void __launch_bounds__(256) softmax_row_kernel(float* __restrict__ P)
{
    int row = blockIdx.x, tid = threadIdx.x;
    float* p = P + (size_t)row * QLEN;
    float x0 = p[tid], x1 = p[tid + 256];
    float m = block_reduce_max(fmaxf(x0, x1));
    float e0 = __expf(x0 - m), e1 = __expf(x1 - m);
    float s = block_reduce_sum(e0 + e1);
    float inv = 1.f / s;
    p[tid] = e0 * inv;
    p[tid + 256] = e1 * inv;
}

__global__ void __launch_bounds__(256) colmax_kernel(
    const float* __restrict__ P, float* __restrict__ re)
{
    int b = blockIdx.x;
    int q = blockIdx.y * 256 + threadIdx.x;
    const float* p = P + (size_t)b * CLEN * QLEN + q;
    float m = -1e30f;
    for (int r = 0; r < CLEN; r++) m = fmaxf(m, p[(size_t)r * QLEN]);
    re[b * QLEN + q] = m;
}

__global__ void fc_kernel(const float* __restrict__ re, const float* __restrict__ w,
                          const float* __restrict__ bfc, float* __restrict__ out)
{
    int t = threadIdx.x;
    if (t >= 8) return;
    int b = t >> 2, o = t & 3;
    float s = bfc[o];
    for (int q = 0; q < QLEN; q++) s += re[b * QLEN + q] * w[q * 4 + o];
    out[b * 4 + o] = s;
}

// ---------------------------------------------------------------------------
// Host orchestration
// ---------------------------------------------------------------------------
extern "C" void kernel_launch(void* const* d_in, const int* in_sizes, int n_in,
                              void* d_out, int out_size)
{
    const int*   q_ids    = (const int*)  d_in[0];
    const int*   c_ids    = (const int*)  d_in[1];
    const int*   q_mask   = (const int*)  d_in[2];
    const int*   c_mask   = (const int*)  d_in[3];
    const float* word_emb = (const float*)d_in[4];
    const float* pos_emb  = (const float*)d_in[5];
    const float* type_emb = (const float*)d_in[6];
    const float* eg       = (const float*)d_in[7];
    const float* eb       = (const float*)d_in[8];
    const float* Wq  = (const float*)d_in[9];
    const float* bq  = (const float*)d_in[10];
    const float* Wk  = (const float*)d_in[11];
    const float* bk  = (const float*)d_in[12];
    const float* Wv  = (const float*)d_in[13];
    const float* bv  = (const float*)d_in[14];
    const float* Wo  = (const float*)d_in[15];
    const float* bo  = (const float*)d_in[16];
    const float* l1g = (const float*)d_in[17];
    const float* l1b = (const float*)d_in[18];
    const float* W1  = (const float*)d_in[19];
    const float* b1  = (const float*)d_in[20];
    const float* W2  = (const float*)d_in[21];
    const float* b2  = (const float*)d_in[22];
    const float* l2g = (const float*)d_in[23];
    const float* l2b = (const float*)d_in[24];
    const float* fcw = (const float*)d_in[25];
    const float* fcb = (const float*)d_in[26];

    cudaFuncSetAttribute(mma_gemm, cudaFuncAttributeMaxDynamicSharedMemorySize, SMEMSZ);

    __nv_bfloat16 *wqkvhi, *wqkvlo, *wohi, *wolo, *w1hi, *w1lo, *w2hi, *w2lo;
    __nv_bfloat16 *hhi, *hlo, *sthi, *stlo, *ffnhi, *ffnlo;
    float *h, *qkv, *t2, *ssc, *sre;
    cudaGetSymbolAddress((void**)&wqkvhi, g_wqkv_hi);
    cudaGetSymbolAddress((void**)&wqkvlo, g_wqkv_lo);
    cudaGetSymbolAddress((void**)&wohi,   g_wo_hi);
    cudaGetSymbolAddress((void**)&wolo,   g_wo_lo);
    cudaGetSymbolAddress((void**)&w1hi,   g_w1_hi);
    cudaGetSymbolAddress((void**)&w1lo,   g_w1_lo);
    cudaGetSymbolAddress((void**)&w2hi,   g_w2_hi);
    cudaGetSymbolAddress((void**)&w2lo,   g_w2_lo);
    cudaGetSymbolAddress((void**)&h,      g_h);
    cudaGetSymbolAddress((void**)&hhi,    g_h_hi);
    cudaGetSymbolAddress((void**)&hlo,    g_h_lo);
    cudaGetSymbolAddress((void**)&qkv,    g_qkv);
    cudaGetSymbolAddress((void**)&t2,     g_t2);
    cudaGetSymbolAddress((void**)&sthi,   g_st_hi);
    cudaGetSymbolAddress((void**)&stlo,   g_st_lo);
    cudaGetSymbolAddress((void**)&ffnhi,  g_ffn_hi);
    cudaGetSymbolAddress((void**)&ffnlo,  g_ffn_lo);
    cudaGetSymbolAddress((void**)&ssc,    g_sc);
    cudaGetSymbolAddress((void**)&sre,    g_re);

    dim3 gQKV(NQKV/128,   ROWSA/128);   // 18 x 40
    dim3 gD  (DMODEL/128, ROWSA/128);   //  6 x 40
    dim3 gF  (FFDIM/128,  ROWSA/128);   // 24 x 40

    // 0: QKV weight prep (all layers, one launch)
    wprep_qkv_all<<<dim3(24, 24, 36), 256>>>(Wq, Wk, Wv, wqkvhi, wqkvlo);
    // 1-2: embeddings (c rows [0,4096), q rows [4096,5120))
    embed_ln_kernel<<<CROWS, 256>>>(c_ids, word_emb, pos_emb, type_emb, eg, eb,
                                    h, hhi, hlo, CLEN, 0);
    embed_ln_kernel<<<QROWS, 256>>>(q_ids, word_emb, pos_emb, type_emb, eg, eb,
                                    h, hhi, hlo, QLEN, QBASE);
    // 3: layer-0 merged QKV GEMM (profiling target)
    mma_gemm<<<gQKV, 256, SMEMSZ>>>(hhi, hlo, wqkvhi, wqkvlo,
        bq, bk, bv, qkv, nullptr, nullptr, ROWSA, NQKV, DMODEL, 3);
    // 4-5: layer-0 attention (c then q)
    local_attn_kernel<<<dim3(CLEN/CHUNK, NHEAD, BATCH), 256>>>(
        qkv, c_mask, sthi, stlo, CLEN/CHUNK, CLEN, 0);
    local_attn_kernel<<<dim3(QLEN/CHUNK, NHEAD, BATCH), 256>>>(
        qkv, q_mask, sthi, stlo, QLEN/CHUNK, QLEN, QBASE);
    // 6-8: remaining weight prep (batched over layers)
    wprep_b<<<dim3(24, 24, NL), 256>>>(Wo, wohi, wolo, DMODEL, DMODEL);
    wprep_b<<<dim3(96, 24, NL), 256>>>(W1, w1hi, w1lo, DMODEL, FFDIM);
    wprep_b<<<dim3(24, 96, NL), 256>>>(W2, w2hi, w2lo, FFDIM, DMODEL);

    for (int l = 0; l < NL; l++) {
        if (l > 0) {
            size_t qb = (size_t)l * QKVW;
            mma_gemm<<<gQKV, 256, SMEMSZ>>>(hhi, hlo, wqkvhi + qb, wqkvlo + qb,
                bq + l*DMODEL, bk + l*DMODEL, bv + l*DMODEL,
                qkv, nullptr, nullptr, ROWSA, NQKV, DMODEL, 3);
            local_attn_kernel<<<dim3(CLEN/CHUNK, NHEAD, BATCH), 256>>>(
                qkv, c_mask, sthi, stlo, CLEN/CHUNK, CLEN, 0);
            local_attn_kernel<<<dim3(QLEN/CHUNK, NHEAD, BATCH), 256>>>(
                qkv, q_mask, sthi, stlo, QLEN/CHUNK, QLEN, QBASE);
        }
        mma_gemm<<<gD, 256, SMEMSZ>>>(sthi, stlo, wohi + l*D2, wolo + l*D2,
            bo + l*DMODEL, nullptr, nullptr, t2, nullptr, nullptr,
            ROWSA, DMODEL, DMODEL, 0);
        add_ln_kernel<<<ROWSA, 256>>>(h, t2, l1g + l*DMODEL, l1b + l*DMODEL, hhi, hlo);
        mma_gemm<<<gF, 256, SMEMSZ>>>(hhi, hlo, w1hi + l*DF, w1lo + l*DF,
            b1 + l*FFDIM, nullptr, nullptr, nullptr, ffnhi, ffnlo,
            ROWSA, FFDIM, DMODEL, 2);
        mma_gemm<<<gD, 256, SMEMSZ>>>(ffnhi, ffnlo, w2hi + l*DF, w2lo + l*DF,
            b2 + l*DMODEL, nullptr, nullptr, t2, nullptr, nullptr,
            ROWSA, DMODEL, FFDIM, 0);
        add_ln_kernel<<<ROWSA, 256>>>(h, t2, l2g + l*DMODEL, l2b + l*DMODEL, hhi, hlo);
    }

    // interaction: scores[b] = c_h[b] @ q_h[b]^T -> [CLEN, QLEN]
    for (int b = 0; b < BATCH; b++) {
        mma_gemm<<<dim3(QLEN/128, CLEN/128), 256, SMEMSZ>>>(
            hhi + (size_t)b*CLEN*DMODEL, hlo + (size_t)b*CLEN*DMODEL,
            hhi + (size_t)(QBASE + b*QLEN)*DMODEL, hlo + (size_t)(QBASE + b*QLEN)*DMODEL,
            nullptr, nullptr, nullptr,
            ssc + (size_t)b*CLEN*QLEN, nullptr, nullptr,
            CLEN, QLEN, DMODEL, 0);
    }
    softmax_row_kernel<<<BATCH * CLEN, 256>>>(ssc);
    colmax_kernel<<<dim3(BATCH, QLEN/256), 256>>>(ssc, sre);
    fc_kernel<<<1, 32>>>(sre, fcw, fcb, (float*)d_out);
}

// round 6
// speedup vs baseline: 1.9221x; 1.2713x over previous
#include <cuda_runtime.h>
#include <cuda_bf16.h>
#include <math.h>
#include <stdint.h>

// ---------------------------------------------------------------------------
// Problem constants
// ---------------------------------------------------------------------------
#define NL     12
#define DMODEL 768
#define NHEAD  12
#define DHEAD  64
#define FFDIM  3072
#define BATCH  2
#define QLEN   512
#define CLEN   2048
#define CHUNK  256
#define WINW   512
#define NQKV   2304
#define CROWS  (BATCH * CLEN)              // 4096
#define QROWS  (BATCH * QLEN)              // 1024
#define ROWSA  (CROWS + QROWS)             // 5120 merged rows
#define QBASE  CROWS

// ---------------------------------------------------------------------------
// PTX helpers (baseline sm_80+ features only)
// ---------------------------------------------------------------------------
__device__ __forceinline__ uint32_t smem_u32(const void* p) {
    uint32_t a;
    asm("{ .reg .u64 t; cvta.to.shared.u64 t, %1; cvt.u32.u64 %0, t; }" : "=r"(a) : "l"(p));
    return a;
}
__device__ __forceinline__ void ldsm_x4(uint32_t* r, uint32_t addr) {
    asm volatile("ldmatrix.sync.aligned.m8n8.x4.shared.b16 {%0,%1,%2,%3}, [%4];"
                 : "=r"(r[0]), "=r"(r[1]), "=r"(r[2]), "=r"(r[3]) : "r"(addr));
}
__device__ __forceinline__ void mma_bf16(float* c, const uint32_t* a, uint32_t b0, uint32_t b1) {
    asm volatile(
        "mma.sync.aligned.m16n8k16.row.col.f32.bf16.bf16.f32 "
        "{%0,%1,%2,%3}, {%4,%5,%6,%7}, {%8,%9}, {%0,%1,%2,%3};"
        : "+f"(c[0]), "+f"(c[1]), "+f"(c[2]), "+f"(c[3])
        : "r"(a[0]), "r"(a[1]), "r"(a[2]), "r"(a[3]), "r"(b0), "r"(b1));
}
#define CP_ASYNC16(dst, src) \
    asm volatile("cp.async.cg.shared.global [%0], [%1], 16;" :: "r"(dst), "l"(src))
#define CP_COMMIT() asm volatile("cp.async.commit_group;")
#define CP_WAIT(n)  asm volatile("cp.async.wait_group %0;" :: "n"(n))

// ---------------------------------------------------------------------------
// Scratch (device globals)
// ---------------------------------------------------------------------------
#define D2   ((size_t)DMODEL * DMODEL)
#define DF   ((size_t)DMODEL * FFDIM)
#define QKVW (3ull * D2)

__device__ __nv_bfloat16 g_wqkv_hi[12 * QKVW];
__device__ __nv_bfloat16 g_wqkv_lo[12 * QKVW];
__device__ __nv_bfloat16 g_wo_hi[12 * D2];
__device__ __nv_bfloat16 g_wo_lo[12 * D2];
__device__ __nv_bfloat16 g_w1_hi[12 * DF];
__device__ __nv_bfloat16 g_w1_lo[12 * DF];
__device__ __nv_bfloat16 g_w2_hi[12 * DF];
__device__ __nv_bfloat16 g_w2_lo[12 * DF];

__device__ float g_h [ROWSA * DMODEL];
__device__ __nv_bfloat16 g_h_hi[ROWSA * DMODEL];
__device__ __nv_bfloat16 g_h_lo[ROWSA * DMODEL];
__device__ float g_qkv[ROWSA * NQKV];
__device__ float g_t2 [ROWSA * DMODEL];
__device__ __nv_bfloat16 g_st_hi[ROWSA * DMODEL];
__device__ __nv_bfloat16 g_st_lo[ROWSA * DMODEL];
__device__ __nv_bfloat16 g_ffn_hi[ROWSA * FFDIM];
__device__ __nv_bfloat16 g_ffn_lo[ROWSA * FFDIM];

__device__ float g_sc [BATCH * CLEN * QLEN];
__device__ float g_re [BATCH * QLEN];

// ---------------------------------------------------------------------------
// Reductions
// ---------------------------------------------------------------------------
__device__ __forceinline__ float block_reduce_sum(float v) {
    __shared__ float sh[33];
    int lane = threadIdx.x & 31, wid = threadIdx.x >> 5;
    #pragma unroll
    for (int o = 16; o; o >>= 1) v += __shfl_xor_sync(0xffffffffu, v, o);
    if (lane == 0) sh[wid] = v;
    __syncthreads();
    if (wid == 0) {
        float t = (lane < 8) ? sh[lane] : 0.f;
        #pragma unroll
        for (int o = 4; o; o >>= 1) t += __shfl_xor_sync(0xffffffffu, t, o);
        if (lane == 0) sh[32] = t;
    }
    __syncthreads();
    float r = sh[32];
    __syncthreads();
    return r;
}
__device__ __forceinline__ float block_reduce_max(float v) {
    __shared__ float sh[33];
    int lane = threadIdx.x & 31, wid = threadIdx.x >> 5;
    #pragma unroll
    for (int o = 16; o; o >>= 1) v = fmaxf(v, __shfl_xor_sync(0xffffffffu, v, o));
    if (lane == 0) sh[wid] = v;
    __syncthreads();
    if (wid == 0) {
        float t = (lane < 8) ? sh[lane] : -1e30f;
        #pragma unroll
        for (int o = 4; o; o >>= 1) t = fmaxf(t, __shfl_xor_sync(0xffffffffu, t, o));
        if (lane == 0) sh[32] = t;
    }
    __syncthreads();
    float r = sh[32];
    __syncthreads();
    return r;
}

__device__ __forceinline__ void split_bf16(float x, __nv_bfloat16& hi, __nv_bfloat16& lo) {
    hi = __float2bfloat16(x);
    lo = __float2bfloat16(x - __bfloat162float(hi));
}

// ---------------------------------------------------------------------------
// Batched weight transpose + split
// ---------------------------------------------------------------------------
__global__ void __launch_bounds__(256) wprep_qkv_all(
    const float* __restrict__ Wq, const float* __restrict__ Wk,
    const float* __restrict__ Wv,
    __nv_bfloat16* __restrict__ Thi, __nv_bfloat16* __restrict__ Tlo)
{
    __shared__ float t[32][33];
    int z = blockIdx.z;
    int l = z / 3, which = z % 3;
    const float* W = (which == 0 ? Wq : (which == 1 ? Wk : Wv)) + (size_t)l * D2;
    __nv_bfloat16* ohi = Thi + (size_t)l * QKVW + (size_t)which * D2;
    __nv_bfloat16* olo = Tlo + (size_t)l * QKVW + (size_t)which * D2;
    int tx = threadIdx.x & 31, ty = threadIdx.x >> 5;
    int n0 = blockIdx.x * 32, k0 = blockIdx.y * 32;
    #pragma unroll
    for (int j = 0; j < 4; j++)
        t[ty + 8 * j][tx] = W[(size_t)(k0 + ty + 8 * j) * DMODEL + n0 + tx];
    __syncthreads();
    #pragma unroll
    for (int j = 0; j < 4; j++) {
        int n = n0 + ty + 8 * j, k = k0 + tx;
        __nv_bfloat16 hi, lo;
        split_bf16(t[tx][ty + 8 * j], hi, lo);
        ohi[(size_t)n * DMODEL + k] = hi;
        olo[(size_t)n * DMODEL + k] = lo;
    }
}

__global__ void __launch_bounds__(256) wprep_b(
    const float* __restrict__ W, __nv_bfloat16* __restrict__ Thi,
    __nv_bfloat16* __restrict__ Tlo, int K, int N)
{
    __shared__ float t[32][33];
    size_t l = blockIdx.z;
    const float* Wl = W + l * (size_t)K * N;
    __nv_bfloat16* ohi = Thi + l * (size_t)K * N;
    __nv_bfloat16* olo = Tlo + l * (size_t)K * N;
    int tx = threadIdx.x & 31, ty = threadIdx.x >> 5;
    int n0 = blockIdx.x * 32, k0 = blockIdx.y * 32;
    #pragma unroll
    for (int j = 0; j < 4; j++)
        t[ty + 8 * j][tx] = Wl[(size_t)(k0 + ty + 8 * j) * N + n0 + tx];
    __syncthreads();
    #pragma unroll
    for (int j = 0; j < 4; j++) {
        int n = n0 + ty + 8 * j, k = k0 + tx;
        __nv_bfloat16 hi, lo;
        split_bf16(t[tx][ty + 8 * j], hi, lo);
        ohi[(size_t)n * K + k] = hi;
        olo[(size_t)n * K + k] = lo;
    }
}

// ---------------------------------------------------------------------------
// Embedding + LN / Add + LN
// ---------------------------------------------------------------------------
__global__ void __launch_bounds__(256) embed_ln_kernel(
    const int* __restrict__ ids, const float* __restrict__ we,
    const float* __restrict__ pe, const float* __restrict__ te,
    const float* __restrict__ g, const float* __restrict__ b,
    float* __restrict__ h, __nv_bfloat16* __restrict__ hhi,
    __nv_bfloat16* __restrict__ hlo, int S, int row_off)
{
    int rlocal = blockIdx.x;
    int s = rlocal % S;
    int tid = threadIdx.x;
    long long id = ids[rlocal];
    const float* w = we + id * DMODEL;
    float x[3];
    #pragma unroll
    for (int l = 0; l < 3; l++) {
        int d = tid + l * 256;
        x[l] = w[d] + pe[(size_t)s * DMODEL + d] + te[d];
    }
    float mean = block_reduce_sum(x[0] + x[1] + x[2]) * (1.f / DMODEL);
    float vs = 0.f;
    #pragma unroll
    for (int l = 0; l < 3; l++) { float dd = x[l] - mean; vs += dd * dd; }
    float rstd = rsqrtf(block_reduce_sum(vs) * (1.f / DMODEL) + 1e-12f);
    size_t base = (size_t)(row_off + rlocal) * DMODEL;
    #pragma unroll
    for (int l = 0; l < 3; l++) {
        int d = tid + l * 256;
        float y = (x[l] - mean) * rstd * g[d] + b[d];
        h[base + d] = y;
        __nv_bfloat16 hi, lo; split_bf16(y, hi, lo);
        hhi[base + d] = hi; hlo[base + d] = lo;
    }
}

__global__ void __launch_bounds__(256) add_ln_kernel(
    float* __restrict__ h, const float* __restrict__ a,
    const float* __restrict__ g, const float* __restrict__ b,
    __nv_bfloat16* __restrict__ hhi, __nv_bfloat16* __restrict__ hlo)
{
    int row = blockIdx.x;
    int tid = threadIdx.x;
    size_t base = (size_t)row * DMODEL;
    float x[3];
    #pragma unroll
    for (int l = 0; l < 3; l++) {
        int d = tid + l * 256;
        x[l] = h[base + d] + a[base + d];
    }
    float mean = block_reduce_sum(x[0] + x[1] + x[2]) * (1.f / DMODEL);
    float vs = 0.f;
    #pragma unroll
    for (int l = 0; l < 3; l++) { float dd = x[l] - mean; vs += dd * dd; }
    float rstd = rsqrtf(block_reduce_sum(vs) * (1.f / DMODEL) + 1e-12f);
    #pragma unroll
    for (int l = 0; l < 3; l++) {
        int d = tid + l * 256;
        float y = (x[l] - mean) * rstd * g[d] + b[d];
        h[base + d] = y;
        __nv_bfloat16 hi, lo; split_bf16(y, hi, lo);
        hhi[base + d] = hi; hlo[base + d] = lo;
    }
}

// ---------------------------------------------------------------------------
// Split-bf16 HMMA GEMM (unchanged from round 5)
// ---------------------------------------------------------------------------
#define TILE_B (128 * 40 * 2)
#define SMEMSZ (8 * TILE_B)

__global__ void __launch_bounds__(256, 2) mma_gemm(
    const __nv_bfloat16* __restrict__ Ahi, const __nv_bfloat16* __restrict__ Alo,
    const __nv_bfloat16* __restrict__ Bhi, const __nv_bfloat16* __restrict__ Blo,
    const float* __restrict__ bias, const float* __restrict__ bias2,
    const float* __restrict__ bias3,
    float* __restrict__ Cf, __nv_bfloat16* __restrict__ Chi, __nv_bfloat16* __restrict__ Clo,
    int M, int N, int K, int epi)
{
    extern __shared__ char smem[];
    uint32_t sbase = smem_u32(smem);
    int tid = threadIdx.x, lane = tid & 31, wid = tid >> 5;
    int wm = wid & 3, wn = wid >> 2;
    int bm = blockIdx.y * 128, bn = blockIdx.x * 128;
    int nkt = K >> 5;

    float acc[2][8][4] = {};

    int lrow = tid >> 2;
    int lc16 = tid & 3;

    auto load_stage = [&](int buf, int kt) {
        int kb = kt * 32 + lc16 * 8;
        uint32_t dbase = sbase + buf * (4 * TILE_B);
        #pragma unroll
        for (int c = 0; c < 2; c++) {
            int row = lrow + c * 64;
            uint32_t so = (uint32_t)(row * 80 + lc16 * 16);
            CP_ASYNC16(dbase + 0 * TILE_B + so, Ahi + (size_t)(bm + row) * K + kb);
            CP_ASYNC16(dbase + 1 * TILE_B + so, Alo + (size_t)(bm + row) * K + kb);
            CP_ASYNC16(dbase + 2 * TILE_B + so, Bhi + (size_t)(bn + row) * K + kb);
            CP_ASYNC16(dbase + 3 * TILE_B + so, Blo + (size_t)(bn + row) * K + kb);
        }
        CP_COMMIT();
    };

    load_stage(0, 0);

    for (int kt = 0; kt < nkt; kt++) {
        int cur = kt & 1;
        if (kt + 1 < nkt) { load_stage(cur ^ 1, kt + 1); CP_WAIT(1); }
        else              { CP_WAIT(0); }
        __syncthreads();

        uint32_t abase = sbase + cur * (4 * TILE_B);
        #pragma unroll
        for (int ks = 0; ks < 2; ks++) {
            uint32_t koff = (uint32_t)((ks * 16 + (lane >> 4) * 8) * 2);
            uint32_t ah[2][4], al[2][4];
            #pragma unroll
            for (int mt = 0; mt < 2; mt++) {
                uint32_t r = abase + (uint32_t)((wm * 32 + mt * 16 + (lane & 15)) * 80) + koff;
                ldsm_x4(ah[mt], r);
                ldsm_x4(al[mt], r + TILE_B);
            }
            uint32_t bh[2][4], bl[2][4];
            {
                uint32_t r = abase + 2 * TILE_B
                           + (uint32_t)((wn * 64 + (lane & 15)) * 80) + koff;
                ldsm_x4(bh[0], r);
                ldsm_x4(bl[0], r + TILE_B);
            }
            #pragma unroll
            for (int nt = 0; nt < 4; nt++) {
                int c = nt & 1;
                if (nt < 3) {
                    uint32_t r = abase + 2 * TILE_B
                               + (uint32_t)((wn * 64 + (nt + 1) * 16 + (lane & 15)) * 80) + koff;
                    ldsm_x4(bh[c ^ 1], r);
                    ldsm_x4(bl[c ^ 1], r + TILE_B);
                }
                #pragma unroll
                for (int mt = 0; mt < 2; mt++) {
                    mma_bf16(acc[mt][nt * 2 + 0], ah[mt], bh[c][0], bh[c][2]);
                    mma_bf16(acc[mt][nt * 2 + 0], ah[mt], bl[c][0], bl[c][2]);
                    mma_bf16(acc[mt][nt * 2 + 0], al[mt], bh[c][0], bh[c][2]);
                    mma_bf16(acc[mt][nt * 2 + 1], ah[mt], bh[c][1], bh[c][3]);
                    mma_bf16(acc[mt][nt * 2 + 1], ah[mt], bl[c][1], bl[c][3]);
                    mma_bf16(acc[mt][nt * 2 + 1], al[mt], bh[c][1], bh[c][3]);
                }
            }
        }
        __syncthreads();
    }

    int g = lane >> 2, t4 = lane & 3;
    #pragma unroll
    for (int mt = 0; mt < 2; mt++) {
        #pragma unroll
        for (int nt = 0; nt < 4; nt++) {
            #pragma unroll
            for (int h8 = 0; h8 < 2; h8++) {
                float* d = acc[mt][nt * 2 + h8];
                int c0 = bn + wn * 64 + nt * 16 + h8 * 8 + t4 * 2;
                #pragma unroll
                for (int rr = 0; rr < 2; rr++) {
                    int r = bm + wm * 32 + mt * 16 + g + rr * 8;
                    float v0 = d[rr * 2 + 0], v1 = d[rr * 2 + 1];
                    if (epi == 3) {
                        if (c0 < DMODEL) {
                            v0 = (v0 + __ldg(bias + c0)) * 0.125f;
                            v1 = (v1 + __ldg(bias + c0 + 1)) * 0.125f;
                        } else if (c0 < 2 * DMODEL) {
                            v0 += __ldg(bias2 + c0 - DMODEL);
                            v1 += __ldg(bias2 + c0 + 1 - DMODEL);
                        } else {
                            v0 += __ldg(bias3 + c0 - 2 * DMODEL);
                            v1 += __ldg(bias3 + c0 + 1 - 2 * DMODEL);
                        }
                    } else if (bias) {
                        v0 += __ldg(bias + c0);
                        v1 += __ldg(bias + c0 + 1);
                    }
                    if (epi == 2) {
                        v0 = 0.5f * v0 * (1.f + erff(v0 * 0.7071067811865476f));
                        v1 = 0.5f * v1 * (1.f + erff(v1 * 0.7071067811865476f));
                        __nv_bfloat16 h0, l0, h1, l1;
                        split_bf16(v0, h0, l0); split_bf16(v1, h1, l1);
                        size_t idx = (size_t)r * N + c0;
                        *(__nv_bfloat162*)&Chi[idx] = __nv_bfloat162(h0, h1);
                        *(__nv_bfloat162*)&Clo[idx] = __nv_bfloat162(l0, l1);
                        continue;
                    }
                    float2 o; o.x = v0; o.y = v1;
                    *(float2*)&Cf[(size_t)r * N + c0] = o;
                }
            }
        }
    }
}

// ---------------------------------------------------------------------------
// Sliding-window attention v2: branchless, smem-staged bias/index tables.
// 128 threads/block (half chunk), 3 blocks/SM target.
// ---------------------------------------------------------------------------
__global__ void __launch_bounds__(128, 3) local_attn_kernel(
    const float* __restrict__ QKV, const int* __restrict__ mask,
    __nv_bfloat16* __restrict__ Ohi, __nv_bfloat16* __restrict__ Olo,
    int nc, int S, int row_base)
{
    int nb = blockIdx.x;
    int n = nb >> 1, half = nb & 1;
    int h = blockIdx.y, b = blockIdx.z;
    int tid = threadIdx.x;
    int i = half * 128 + tid;                 // query index within chunk
    int qrow = row_base + b * S + n * CHUNK + i;

    __shared__ float sbias[3 * CHUNK];
    __shared__ int   skpos[3 * CHUNK];
    #pragma unroll
    for (int jj = 0; jj < 6; jj++) {
        int j = tid + jj * 128;
        int cn = n - 1 + (j >> 8);
        bool cv = (cn >= 0) && (cn < nc);
        int cnc = min(max(cn, 0), nc - 1);
        int kpos = cnc * CHUNK + (j & 255);
        bool v = cv && (mask[b * S + kpos] != 0);
        sbias[j] = v ? 0.f : -1e30f;
        skpos[j] = kpos;
    }
    __syncthreads();

    const float* qp = QKV + (size_t)qrow * NQKV + h * DHEAD;
    float q[DHEAD];
    #pragma unroll
    for (int d4 = 0; d4 < 16; d4++) {
        float4 t = *(const float4*)(qp + d4 * 4);
        q[d4*4+0] = t.x; q[d4*4+1] = t.y; q[d4*4+2] = t.z; q[d4*4+3] = t.w;
    }

    float m = -1e30f, l = 0.f;
    float acc[DHEAD];
    #pragma unroll
    for (int d = 0; d < DHEAD; d++) acc[d] = 0.f;

    int lane0 = i & ~31;
    int js = lane0, je = lane0 + 31 + WINW;
    // clip to chunks that exist at all
    int jlo = (n == 0) ? CHUNK : 0;
    int jhi = (n == nc - 1) ? (2 * CHUNK - 1) : (3 * CHUNK - 1);
    js = max(js, jlo); je = min(je, jhi);

    const float* kvbase = QKV + (size_t)(row_base + b * S) * NQKV + DMODEL + h * DHEAD;

    for (int j = js; j <= je; j++) {
        float sb = sbias[j];
        const float* kp = kvbase + (size_t)skpos[j] * NQKV;
        float s0 = 0.f, s1 = 0.f, s2 = 0.f, s3 = 0.f;
        #pragma unroll
        for (int d4 = 0; d4 < 16; d4++) {
            float4 kv = *(const float4*)(kp + d4 * 4);
            s0 += q[d4*4+0] * kv.x;
            s1 += q[d4*4+1] * kv.y;
            s2 += q[d4*4+2] * kv.z;
            s3 += q[d4*4+3] * kv.w;
        }
        float bandb = (j >= i && j <= i + WINW) ? 0.f : -1e30f;
        float s = (s0 + s1) + (s2 + s3) + sb + bandb;

        if (s > m) {                          // rare after warmup
            float corr = __expf(m - s);
            l *= corr;
            #pragma unroll
            for (int d = 0; d < DHEAD; d++) acc[d] *= corr;
            m = s;
        }
        float p = __expf(s - m);              // masked j: exp(-1e30) = 0
        l += p;
        const float* vp = kp + DMODEL;
        #pragma unroll
        for (int d4 = 0; d4 < 16; d4++) {
            float4 vv = *(const float4*)(vp + d4 * 4);
            acc[d4*4+0] += p * vv.x;
            acc[d4*4+1] += p * vv.y;
            acc[d4*4+2] += p * vv.z;
            acc[d4*4+3] += p * vv.w;
        }
    }
    float inv = 1.f / l;
    size_t ob = (size_t)qrow * DMODEL + h * DHEAD;
    #pragma unroll
    for (int d = 0; d < DHEAD; d += 2) {
        float v0 = acc[d] * inv, v1 = acc[d+1] * inv;
        __nv_bfloat16 h0, l0, h1, l1;
        split_bf16(v0, h0, l0); split_bf16(v1, h1, l1);
        *(__nv_bfloat162*)&Ohi[ob + d] = __nv_bfloat162(h0, h1);
        *(__nv_bfloat162*)&Olo[ob + d] = __nv_bfloat162(l0, l1);
    }
}

// ---------------------------------------------------------------------------
// Interaction head: softmax row + fused column-max via atomicMax (positive floats)
// ---------------------------------------------------------------------------
__global__ void init_re_kernel(float* __restrict__ re)
{
    re[blockIdx.x * 256 + threadIdx.x] = 0.f;
}

__global__ void __launch_bounds__(256) softmax_max_kernel(
    const float* __restrict__ P, float* __restrict__ re)
{
    int row = blockIdx.x, tid = threadIdx.x;    // row over BATCH*CLEN
    int b = row / CLEN;
    const float* p = P + (size_t)row * QLEN;
    float x0 = p[tid], x1 = p[tid + 256];
    float m = block_reduce_max(fmaxf(x0, x1));
    float e0 = __expf(x0 - m), e1 = __expf(x1 - m);
    float s = block_reduce_sum(e0 + e1);
    float inv = 1.f / s;
    unsigned* r = (unsigned*)(re + b * QLEN);
    atomicMax(r + tid,       __float_as_uint(e0 * inv));
    atomicMax(r + tid + 256, __float_as_uint(e1 * inv));
}

__global__ void fc_kernel(const float* __restrict__ re, const float* __restrict__ w,
                          const float* __restrict__ bfc, float* __restrict__ out)
{
    int t = threadIdx.x;
    if (t >= 8) return;
    int b = t >> 2, o = t & 3;
    float s = bfc[o];
    for (int q = 0; q < QLEN; q++) s += re[b * QLEN + q] * w[q * 4 + o];
    out[b * 4 + o] = s;
}

// ---------------------------------------------------------------------------
// Host orchestration
// ---------------------------------------------------------------------------
extern "C" void kernel_launch(void* const* d_in, const int* in_sizes, int n_in,
                              void* d_out, int out_size)
{
    const int*   q_ids    = (const int*)  d_in[0];
    const int*   c_ids    = (const int*)  d_in[1];
    const int*   q_mask   = (const int*)  d_in[2];
    const int*   c_mask   = (const int*)  d_in[3];
    const float* word_emb = (const float*)d_in[4];
    const float* pos_emb  = (const float*)d_in[5];
    const float* type_emb = (const float*)d_in[6];
    const float* eg       = (const float*)d_in[7];
    const float* eb       = (const float*)d_in[8];
    const float* Wq  = (const float*)d_in[9];
    const float* bq  = (const float*)d_in[10];
    const float* Wk  = (const float*)d_in[11];
    const float* bk  = (const float*)d_in[12];
    const float* Wv  = (const float*)d_in[13];
    const float* bv  = (const float*)d_in[14];
    const float* Wo  = (const float*)d_in[15];
    const float* bo  = (const float*)d_in[16];
    const float* l1g = (const float*)d_in[17];
    const float* l1b = (const float*)d_in[18];
    const float* W1  = (const float*)d_in[19];
    const float* b1  = (const float*)d_in[20];
    const float* W2  = (const float*)d_in[21];
    const float* b2  = (const float*)d_in[22];
    const float* l2g = (const float*)d_in[23];
    const float* l2b = (const float*)d_in[24];
    const float* fcw = (const float*)d_in[25];
    const float* fcb = (const float*)d_in[26];

    cudaFuncSetAttribute(mma_gemm, cudaFuncAttributeMaxDynamicSharedMemorySize, SMEMSZ);

    __nv_bfloat16 *wqkvhi, *wqkvlo, *wohi, *wolo, *w1hi, *w1lo, *w2hi, *w2lo;
    __nv_bfloat16 *hhi, *hlo, *sthi, *stlo, *ffnhi, *ffnlo;
    float *h, *qkv, *t2, *ssc, *sre;
    cudaGetSymbolAddress((void**)&wqkvhi, g_wqkv_hi);
    cudaGetSymbolAddress((void**)&wqkvlo, g_wqkv_lo);
    cudaGetSymbolAddress((void**)&wohi,   g_wo_hi);
    cudaGetSymbolAddress((void**)&wolo,   g_wo_lo);
    cudaGetSymbolAddress((void**)&w1hi,   g_w1_hi);
    cudaGetSymbolAddress((void**)&w1lo,   g_w1_lo);
    cudaGetSymbolAddress((void**)&w2hi,   g_w2_hi);
    cudaGetSymbolAddress((void**)&w2lo,   g_w2_lo);
    cudaGetSymbolAddress((void**)&h,      g_h);
    cudaGetSymbolAddress((void**)&hhi,    g_h_hi);
    cudaGetSymbolAddress((void**)&hlo,    g_h_lo);
    cudaGetSymbolAddress((void**)&qkv,    g_qkv);
    cudaGetSymbolAddress((void**)&t2,     g_t2);
    cudaGetSymbolAddress((void**)&sthi,   g_st_hi);
    cudaGetSymbolAddress((void**)&stlo,   g_st_lo);
    cudaGetSymbolAddress((void**)&ffnhi,  g_ffn_hi);
    cudaGetSymbolAddress((void**)&ffnlo,  g_ffn_lo);
    cudaGetSymbolAddress((void**)&ssc,    g_sc);
    cudaGetSymbolAddress((void**)&sre,    g_re);

    dim3 gQKV(NQKV/128,   ROWSA/128);
    dim3 gD  (DMODEL/128, ROWSA/128);
    dim3 gF  (FFDIM/128,  ROWSA/128);
    dim3 gAc(2*CLEN/CHUNK, NHEAD, BATCH);   // 16 x 12 x 2 = 384 blocks
    dim3 gAq(2*QLEN/CHUNK, NHEAD, BATCH);   //  4 x 12 x 2 =  96 blocks

    // 0: QKV weight prep
    wprep_qkv_all<<<dim3(24, 24, 36), 256>>>(Wq, Wk, Wv, wqkvhi, wqkvlo);
    // 1-2: embeddings
    embed_ln_kernel<<<CROWS, 256>>>(c_ids, word_emb, pos_emb, type_emb, eg, eb,
                                    h, hhi, hlo, CLEN, 0);
    embed_ln_kernel<<<QROWS, 256>>>(q_ids, word_emb, pos_emb, type_emb, eg, eb,
                                    h, hhi, hlo, QLEN, QBASE);
    // 3: layer-0 merged QKV GEMM
    mma_gemm<<<gQKV, 256, SMEMSZ>>>(hhi, hlo, wqkvhi, wqkvlo,
        bq, bk, bv, qkv, nullptr, nullptr, ROWSA, NQKV, DMODEL, 3);
    // 4-5: layer-0 attention (profiling targets)
    local_attn_kernel<<<gAc, 128>>>(qkv, c_mask, sthi, stlo, CLEN/CHUNK, CLEN, 0);
    local_attn_kernel<<<gAq, 128>>>(qkv, q_mask, sthi, stlo, QLEN/CHUNK, QLEN, QBASE);
    // 6-8: remaining weight prep
    wprep_b<<<dim3(24, 24, NL), 256>>>(Wo, wohi, wolo, DMODEL, DMODEL);
    wprep_b<<<dim3(96, 24, NL), 256>>>(W1, w1hi, w1lo, DMODEL, FFDIM);
    wprep_b<<<dim3(24, 96, NL), 256>>>(W2, w2hi, w2lo, FFDIM, DMODEL);

    for (int l = 0; l < NL; l++) {
        if (l > 0) {
            size_t qb = (size_t)l * QKVW;
            mma_gemm<<<gQKV, 256, SMEMSZ>>>(hhi, hlo, wqkvhi + qb, wqkvlo + qb,
                bq + l*DMODEL, bk + l*DMODEL, bv + l*DMODEL,
                qkv, nullptr, nullptr, ROWSA, NQKV, DMODEL, 3);
            local_attn_kernel<<<gAc, 128>>>(qkv, c_mask, sthi, stlo, CLEN/CHUNK, CLEN, 0);
            local_attn_kernel<<<gAq, 128>>>(qkv, q_mask, sthi, stlo, QLEN/CHUNK, QLEN, QBASE);
        }
        mma_gemm<<<gD, 256, SMEMSZ>>>(sthi, stlo, wohi + l*D2, wolo + l*D2,
            bo + l*DMODEL, nullptr, nullptr, t2, nullptr, nullptr,
            ROWSA, DMODEL, DMODEL, 0);
        add_ln_kernel<<<ROWSA, 256>>>(h, t2, l1g + l*DMODEL, l1b + l*DMODEL, hhi, hlo);
        mma_gemm<<<gF, 256, SMEMSZ>>>(hhi, hlo, w1hi + l*DF, w1lo + l*DF,
            b1 + l*FFDIM, nullptr, nullptr, nullptr, ffnhi, ffnlo,
            ROWSA, FFDIM, DMODEL, 2);
        mma_gemm<<<gD, 256, SMEMSZ>>>(ffnhi, ffnlo, w2hi + l*DF, w2lo + l*DF,
            b2 + l*DMODEL, nullptr, nullptr, t2, nullptr, nullptr,
            ROWSA, DMODEL, FFDIM, 0);
        add_ln_kernel<<<ROWSA, 256>>>(h, t2, l2g + l*DMODEL, l2b + l*DMODEL, hhi, hlo);
    }

    // interaction: scores[b] = c_h[b] @ q_h[b]^T -> [CLEN, QLEN]
    for (int b = 0; b < BATCH; b++) {
        mma_gemm<<<dim3(QLEN/128, CLEN/128), 256, SMEMSZ>>>(
            hhi + (size_t)b*CLEN*DMODEL, hlo + (size_t)b*CLEN*DMODEL,
            hhi + (size_t)(QBASE + b*QLEN)*DMODEL, hlo + (size_t)(QBASE + b*QLEN)*DMODEL,
            nullptr, nullptr, nullptr,
            ssc + (size_t)b*CLEN*QLEN, nullptr, nullptr,
            CLEN, QLEN, DMODEL, 0);
    }
    init_re_kernel<<<BATCH * QLEN / 256, 256>>>(sre);
    softmax_max_kernel<<<BATCH * CLEN, 256>>>(ssc, sre);
    fc_kernel<<<1, 32>>>(sre, fcw, fcb, (float*)d_out);
}